// round 12
// baseline (speedup 1.0000x reference)
#include <cuda_runtime.h>
#include <cuda_bf16.h>
#include <math.h>
#include <stdint.h>

#define N0v 20000
#define N1v 20000
#define NNODE 40000
#define F0v 512
#define HIDv 64
#define EPM 200000
#define BTv 8192
#define NPv 4

// ---------------- scratch (static device globals; no allocation) -------------
__device__ __align__(16) float g_feat[NNODE * HIDv];     // 10.24 MB
__device__ __align__(16) float g_s[NPv * BTv * 8];       // seg sum of exp(e)
__device__ __align__(16) float g_ret[NPv * BTv * HIDv];  // seg sum of exp(e)*eft
__device__ __align__(16) float g_fr[2 * 3 * 64];         // [side][l][k-pair re/im]
__device__ float g_score[4];

// ================= mma.sync helpers (arch-neutral HMMA path) ================
__device__ __forceinline__ uint32_t smem_u32(const void* p) {
    uint32_t a;
    asm("{ .reg .u64 t; cvta.to.shared.u64 t, %1; cvt.u32.u64 %0, t; }" : "=r"(a) : "l"(p));
    return a;
}
__device__ __forceinline__ void ldsm4(uint32_t addr, uint32_t* r) {
    asm volatile("ldmatrix.sync.aligned.m8n8.x4.shared.b16 {%0,%1,%2,%3}, [%4];"
        : "=r"(r[0]), "=r"(r[1]), "=r"(r[2]), "=r"(r[3]) : "r"(addr));
}
__device__ __forceinline__ void mma16816(float* d, const uint32_t* a, const uint32_t* b) {
    asm volatile(
        "mma.sync.aligned.m16n8k16.row.col.f32.bf16.bf16.f32 "
        "{%0,%1,%2,%3}, {%4,%5,%6,%7}, {%8,%9}, {%0,%1,%2,%3};"
        : "+f"(d[0]), "+f"(d[1]), "+f"(d[2]), "+f"(d[3])
        : "r"(a[0]), "r"(a[1]), "r"(a[2]), "r"(a[3]), "r"(b[0]), "r"(b[1]));
}
__device__ __forceinline__ void split2(float a, float b, uint32_t& hi, uint32_t& lo) {
    __nv_bfloat16 ha = __float2bfloat16(a), hb = __float2bfloat16(b);
    __nv_bfloat16 la = __float2bfloat16(a - __bfloat162float(ha));
    __nv_bfloat16 lb = __float2bfloat16(b - __bfloat162float(hb));
    hi = ((uint32_t)__bfloat16_as_ushort(hb) << 16) | (uint32_t)__bfloat16_as_ushort(ha);
    lo = ((uint32_t)__bfloat16_as_ushort(lb) << 16) | (uint32_t)__bfloat16_as_ushort(la);
}
__device__ __forceinline__ uint32_t pack_bf2(float a, float b) {
    __nv_bfloat16 ha = __float2bfloat16(a), hb = __float2bfloat16(b);
    return ((uint32_t)__bfloat16_as_ushort(hb) << 16) | (uint32_t)__bfloat16_as_ushort(ha);
}

#define LDA 72          // bf16 elems per smem row (144 B = 9*16, ldmatrix-legal)
#define OF_AHI 0        // A hi: 128 x 72 bf16 = 18432 B
#define OF_BHI 18432    // B hi: 64 x 72 bf16 = 9216 B
#define OF_BLO 27648    // B lo
#define SMTOT  36864

// ------- tower via mma.sync (A bf16, B split) + fused init -------------------
__global__ __launch_bounds__(256) void k_tower_mma(
    const float* __restrict__ feats0, const float* __restrict__ feats1,
    const float* __restrict__ pw0, const float* __restrict__ pb0,
    const float* __restrict__ w20, const float* __restrict__ b20,
    const float* __restrict__ gg0, const float* __restrict__ be0,
    const float* __restrict__ pw1, const float* __restrict__ pb1,
    const float* __restrict__ w21, const float* __restrict__ b21,
    const float* __restrict__ gg1, const float* __restrict__ be1,
    const int* __restrict__ idx0, const int* __restrict__ idx1,
    const float* __restrict__ r_vec)
{
    extern __shared__ __align__(16) char sm[];
    uint32_t sbase = smem_u32(sm);
    int tid = threadIdx.x;
    int lane = tid & 31;
    int wid = tid >> 5;

    // ---- fused init: zero accumulators (grid-strided), g_fr on block 0 ------
    {
        int gt = blockIdx.x * 256 + tid;
        int gstride = gridDim.x * 256;
        float4 z4 = make_float4(0.f, 0.f, 0.f, 0.f);
        for (int i = gt; i < NPv * BTv * HIDv / 4; i += gstride)
            ((float4*)g_ret)[i] = z4;
        for (int i = gt; i < NPv * BTv * 8 / 4; i += gstride)
            ((float4*)g_s)[i] = z4;
        if (blockIdx.x == 0) {
            if (tid < 4) g_score[tid] = 0.f;
            if (tid < 32) {
                int k = tid;
                float rr = r_vec[k * 2 + 0], ri = r_vec[k * 2 + 1];
                float nm = sqrtf(rr * rr + ri * ri);
                float cr = rr / nm, ci = ri / nm;
                float u1r = cr,  u1i = -ci;
                float u0r = u1r * cr - u1i * ci;
                float u0i = u1r * ci + u1i * cr;
                g_fr[(0 * 3 + 0) * 64 + 2 * k] = u0r; g_fr[(0 * 3 + 0) * 64 + 2 * k + 1] = u0i;
                g_fr[(0 * 3 + 1) * 64 + 2 * k] = u1r; g_fr[(0 * 3 + 1) * 64 + 2 * k + 1] = u1i;
                g_fr[(0 * 3 + 2) * 64 + 2 * k] = 1.f; g_fr[(0 * 3 + 2) * 64 + 2 * k + 1] = 0.f;
                float i1r = cr,  i1i = ci;
                float i0r = i1r * cr - i1i * (-ci);
                float i0i = i1r * (-ci) + i1i * cr;
                g_fr[(1 * 3 + 0) * 64 + 2 * k] = i0r; g_fr[(1 * 3 + 0) * 64 + 2 * k + 1] = i0i;
                g_fr[(1 * 3 + 1) * 64 + 2 * k] = i1r; g_fr[(1 * 3 + 1) * 64 + 2 * k + 1] = i1i;
                g_fr[(1 * 3 + 2) * 64 + 2 * k] = 1.f; g_fr[(1 * 3 + 2) * 64 + 2 * k + 1] = 0.f;
            }
        }
    }

    const int NB0 = (N0v + 127) / 128;
    int bt = blockIdx.x;
    int tower = (bt >= NB0) ? 1 : 0;
    int bl = tower ? bt - NB0 : bt;
    int nbase = bl * 128;
    int Nlim = tower ? N1v : N0v;
    int valid = Nlim - nbase; if (valid > 128) valid = 128;
    const float* X  = tower ? feats1 : feats0;
    const float* PW = tower ? pw1 : pw0;
    const float* PB = tower ? pb1 : pb0;
    const float* W2 = tower ? w21 : w20;
    const float* B2 = tower ? b21 : b20;
    const float* GG = tower ? gg1 : gg0;
    const float* BE = tower ? be1 : be0;
    const int*  IDX = tower ? idx1 : idx0;

    int ra    = lane & 15;
    int kadd  = (lane >> 4) * 8;
    int nB    = ((lane >> 4) << 3) + (lane & 7);
    int kB    = ((lane >> 3) & 1) * 8;

    float acc[8][4];
    #pragma unroll
    for (int nt = 0; nt < 8; nt++)
        #pragma unroll
        for (int i = 0; i < 4; i++) acc[nt][i] = 0.f;

    // =================== GEMM1: X[128x512] @ W1[512x64] ======================
    for (int c = 0; c < 8; c++) {
        #pragma unroll
        for (int it = 0; it < 8; it++) {
            int idx = tid + it * 256;
            int row = idx >> 4, q = idx & 15;
            int gr = nbase + row; if (gr >= Nlim) gr = Nlim - 1;
            float4 v = *(const float4*)&X[(size_t)gr * F0v + c * 64 + q * 4];
            uint2 H;
            H.x = pack_bf2(v.x, v.y);
            H.y = pack_bf2(v.z, v.w);
            uint32_t off = (uint32_t)(row * LDA + q * 4) * 2;
            *(uint2*)(sm + OF_AHI + off) = H;
        }
        #pragma unroll
        for (int it = 0; it < 4; it++) {
            int idx = tid + it * 256;
            int k = idx >> 4, q = (idx & 15) * 4;
            float4 w = *(const float4*)&PW[(size_t)(c * 64 + k) * HIDv + q];
            float wv[4] = {w.x, w.y, w.z, w.w};
            #pragma unroll
            for (int j = 0; j < 4; j++) {
                int n = q + j;
                int kp = k ^ (((n >> 3) & 7) << 3);
                __nv_bfloat16 h = __float2bfloat16(wv[j]);
                __nv_bfloat16 l = __float2bfloat16(wv[j] - __bfloat162float(h));
                uint32_t off = (uint32_t)(n * LDA + kp) * 2;
                *(__nv_bfloat16*)(sm + OF_BHI + off) = h;
                *(__nv_bfloat16*)(sm + OF_BLO + off) = l;
            }
        }
        __syncthreads();
        #pragma unroll
        for (int ks = 0; ks < 4; ks++) {
            uint32_t ahi[4], bh[16], blo[16];
            uint32_t aoff = (uint32_t)((wid * 16 + ra) * LDA + ks * 16 + kadd) * 2;
            ldsm4(sbase + OF_AHI + aoff, ahi);
            #pragma unroll
            for (int ng = 0; ng < 4; ng++) {
                int n = ng * 16 + nB;
                int kp = (ks * 16 + kB) ^ (((n >> 3) & 7) << 3);
                uint32_t boff = (uint32_t)(n * LDA + kp) * 2;
                ldsm4(sbase + OF_BHI + boff, &bh[ng * 4]);
                ldsm4(sbase + OF_BLO + boff, &blo[ng * 4]);
            }
            #pragma unroll
            for (int nt = 0; nt < 8; nt++) {
                mma16816(acc[nt], ahi, &bh[nt * 2]);
                mma16816(acc[nt], ahi, &blo[nt * 2]);
            }
        }
        __syncthreads();
    }

    // =================== z = acc + b1; h = gelu(z) -> A smem =================
    int nlo = 2 * (lane & 3);
    int r0 = wid * 16 + (lane >> 2);
    int r1 = r0 + 8;
    float z[8][4];
    #pragma unroll
    for (int nt = 0; nt < 8; nt++) {
        float b0 = PB[nt * 8 + nlo], b1v = PB[nt * 8 + nlo + 1];
        z[nt][0] = acc[nt][0] + b0;  z[nt][1] = acc[nt][1] + b1v;
        z[nt][2] = acc[nt][2] + b0;  z[nt][3] = acc[nt][3] + b1v;
        float h0 = 0.5f * z[nt][0] * (1.f + erff(z[nt][0] * 0.70710678118654752f));
        float h1 = 0.5f * z[nt][1] * (1.f + erff(z[nt][1] * 0.70710678118654752f));
        float h2 = 0.5f * z[nt][2] * (1.f + erff(z[nt][2] * 0.70710678118654752f));
        float h3 = 0.5f * z[nt][3] * (1.f + erff(z[nt][3] * 0.70710678118654752f));
        uint32_t o0 = (uint32_t)(r0 * LDA + nt * 8 + nlo) * 2;
        uint32_t o1 = (uint32_t)(r1 * LDA + nt * 8 + nlo) * 2;
        *(uint32_t*)(sm + OF_AHI + o0) = pack_bf2(h0, h1);
        *(uint32_t*)(sm + OF_AHI + o1) = pack_bf2(h2, h3);
        acc[nt][0] = 0.f; acc[nt][1] = 0.f; acc[nt][2] = 0.f; acc[nt][3] = 0.f;
    }
    #pragma unroll
    for (int it = 0; it < 4; it++) {
        int idx = tid + it * 256;
        int k = idx >> 4, q = (idx & 15) * 4;
        float4 w = *(const float4*)&W2[(size_t)k * HIDv + q];
        float wv[4] = {w.x, w.y, w.z, w.w};
        #pragma unroll
        for (int j = 0; j < 4; j++) {
            int n = q + j;
            int kp = k ^ (((n >> 3) & 7) << 3);
            __nv_bfloat16 h = __float2bfloat16(wv[j]);
            __nv_bfloat16 l = __float2bfloat16(wv[j] - __bfloat162float(h));
            uint32_t off = (uint32_t)(n * LDA + kp) * 2;
            *(__nv_bfloat16*)(sm + OF_BHI + off) = h;
            *(__nv_bfloat16*)(sm + OF_BLO + off) = l;
        }
    }
    __syncthreads();

    // =================== GEMM2: h[128x64] @ W2[64x64] ========================
    #pragma unroll
    for (int ks = 0; ks < 4; ks++) {
        uint32_t ahi[4], bh[16], blo[16];
        uint32_t aoff = (uint32_t)((wid * 16 + ra) * LDA + ks * 16 + kadd) * 2;
        ldsm4(sbase + OF_AHI + aoff, ahi);
        #pragma unroll
        for (int ng = 0; ng < 4; ng++) {
            int n = ng * 16 + nB;
            int kp = (ks * 16 + kB) ^ (((n >> 3) & 7) << 3);
            uint32_t boff = (uint32_t)(n * LDA + kp) * 2;
            ldsm4(sbase + OF_BHI + boff, &bh[ng * 4]);
            ldsm4(sbase + OF_BLO + boff, &blo[ng * 4]);
        }
        #pragma unroll
        for (int nt = 0; nt < 8; nt++) {
            mma16816(acc[nt], ahi, &bh[nt * 2]);
            mma16816(acc[nt], ahi, &blo[nt * 2]);
        }
    }

    // =================== y = acc + b2 + z; LayerNorm; store ==================
    float y[8][4];
    float s1a = 0.f, s2a = 0.f, s1b = 0.f, s2b = 0.f;
    #pragma unroll
    for (int nt = 0; nt < 8; nt++) {
        float b0 = B2[nt * 8 + nlo], b1v = B2[nt * 8 + nlo + 1];
        y[nt][0] = acc[nt][0] + b0 + z[nt][0];
        y[nt][1] = acc[nt][1] + b1v + z[nt][1];
        y[nt][2] = acc[nt][2] + b0 + z[nt][2];
        y[nt][3] = acc[nt][3] + b1v + z[nt][3];
        s1a += y[nt][0] + y[nt][1];
        s2a += y[nt][0] * y[nt][0] + y[nt][1] * y[nt][1];
        s1b += y[nt][2] + y[nt][3];
        s2b += y[nt][2] * y[nt][2] + y[nt][3] * y[nt][3];
    }
    #pragma unroll
    for (int m = 1; m < 4; m <<= 1) {
        s1a += __shfl_xor_sync(0xffffffffu, s1a, m);
        s2a += __shfl_xor_sync(0xffffffffu, s2a, m);
        s1b += __shfl_xor_sync(0xffffffffu, s1b, m);
        s2b += __shfl_xor_sync(0xffffffffu, s2b, m);
    }
    float mu0 = s1a * (1.f / 64.f);
    float rs0 = rsqrtf(s2a * (1.f / 64.f) - mu0 * mu0 + 1e-5f);
    float mu1 = s1b * (1.f / 64.f);
    float rs1 = rsqrtf(s2b * (1.f / 64.f) - mu1 * mu1 + 1e-5f);
    if (r0 < valid) {
        int gn = IDX[nbase + r0];
        #pragma unroll
        for (int nt = 0; nt < 8; nt++) {
            float2 o;
            o.x = (y[nt][0] - mu0) * rs0 * GG[nt * 8 + nlo] + BE[nt * 8 + nlo];
            o.y = (y[nt][1] - mu0) * rs0 * GG[nt * 8 + nlo + 1] + BE[nt * 8 + nlo + 1];
            *(float2*)&g_feat[(size_t)gn * HIDv + nt * 8 + nlo] = o;
        }
    }
    if (r1 < valid) {
        int gn = IDX[nbase + r1];
        #pragma unroll
        for (int nt = 0; nt < 8; nt++) {
            float2 o;
            o.x = (y[nt][2] - mu1) * rs1 * GG[nt * 8 + nlo] + BE[nt * 8 + nlo];
            o.y = (y[nt][3] - mu1) * rs1 * GG[nt * 8 + nlo + 1] + BE[nt * 8 + nlo + 1];
            *(float2*)&g_feat[(size_t)gn * HIDv + nt * 8 + nlo] = o;
        }
    }
}

// ---- fused metapath: gather+rotate+mean -> e -> exp -> seg sums (no max) ----
__global__ __launch_bounds__(256) void k_mpf(
    const int* __restrict__ emi_u, const int* __restrict__ tgt_u,
    const int* __restrict__ emi_i, const int* __restrict__ tgt_i,
    const float* __restrict__ attn_u, const float* __restrict__ attn_i)
{
    int warp = blockIdx.x * (blockDim.x >> 5) + (threadIdx.x >> 5);
    int lane = threadIdx.x & 31;
    int half = lane >> 4;
    int sl = lane & 15;
    int inst = warp * 2 + half;
    int p = inst / EPM;
    int i = inst - p * EPM;
    int side = p >> 1, pl = p & 1;
    const int* emi = side ? emi_i : emi_u;
    const int* tgt = side ? tgt_i : tgt_u;
    const float* attn = side ? attn_i : attn_u;

    int n = 0;
    if (sl < 3) n = emi[((size_t)pl * EPM + i) * 3 + sl];
    float re0 = 0.f, im0 = 0.f, re1 = 0.f, im1 = 0.f;
    #pragma unroll
    for (int l = 0; l < 3; l++) {
        int nl = __shfl_sync(0xffffffffu, n, half * 16 + l);
        float4 v  = *(const float4*)&g_feat[(size_t)nl * HIDv + sl * 4];
        float4 fr = *(const float4*)&g_fr[(side * 3 + l) * 64 + sl * 4];
        re0 += v.x * fr.x - v.y * fr.y;
        im0 += v.x * fr.y + v.y * fr.x;
        re1 += v.z * fr.z - v.w * fr.w;
        im1 += v.z * fr.w + v.w * fr.z;
    }
    re0 *= (1.f / 3.f); im0 *= (1.f / 3.f);
    re1 *= (1.f / 3.f); im1 *= (1.f / 3.f);

    int h = sl >> 1;
    int dpart = (sl & 1) * 4;
    float4 av = *(const float4*)&attn[(pl * 8 + h) * 8 + dpart];
    float ep = re0 * av.x + im0 * av.y + re1 * av.z + im1 * av.w;
    ep += __shfl_xor_sync(0xffffffffu, ep, 1);
    float ev = ep > 0.f ? ep : 0.01f * ep;
    float a = __expf(ev);

    int t = tgt[(size_t)pl * EPM + i];
    size_t seg = (size_t)p * BTv + t;
    if ((sl & 1) == 0) atomicAdd(&g_s[seg * 8 + h], a);
    atomicAdd((float4*)&g_ret[seg * HIDv + sl * 4],
              make_float4(a * re0, a * im0, a * re1, a * im1));
}

// -------- semantic via mma.sync (A bf16, B split): 128x128 per block ---------
#define S_LDA 72
#define S_AHI 0          // 128 x 72 bf16 = 18432
#define S_BHI 18432      // 128 n x 72 k = 18432
#define S_BLO 36864
#define S_TOT 55296

__global__ __launch_bounds__(256) void k_sem_mma(
    const float* __restrict__ su_w1, const float* __restrict__ su_b1, const float* __restrict__ su_w2,
    const float* __restrict__ si_w1, const float* __restrict__ si_b1, const float* __restrict__ si_w2)
{
    extern __shared__ __align__(16) char sm2[];
    uint32_t sbase = smem_u32(sm2);
    __shared__ float red[8];
    int p = blockIdx.y;
    const float* w1 = (p < 2) ? su_w1 : si_w1;
    const float* b1 = (p < 2) ? su_b1 : si_b1;
    const float* w2 = (p < 2) ? su_w2 : si_w2;
    int tid = threadIdx.x;
    int lane = tid & 31;
    int wid = tid >> 5;

    #pragma unroll
    for (int it = 0; it < 8; it++) {
        int idx = tid + it * 256;
        int k = idx >> 5;
        int q = (idx & 31) * 4;
        float4 w = *(const float4*)&w1[(size_t)k * 128 + q];
        float wv[4] = {w.x, w.y, w.z, w.w};
        #pragma unroll
        for (int j = 0; j < 4; j++) {
            int n = q + j;
            int kp = k ^ (((n >> 3) & 7) << 3);
            __nv_bfloat16 h = __float2bfloat16(wv[j]);
            __nv_bfloat16 l = __float2bfloat16(wv[j] - __bfloat162float(h));
            uint32_t off = (uint32_t)(n * S_LDA + kp) * 2;
            *(__nv_bfloat16*)(sm2 + S_BHI + off) = h;
            *(__nv_bfloat16*)(sm2 + S_BLO + off) = l;
        }
    }
    {
        int row = tid >> 1;
        int b_g = blockIdx.x * 128 + row;
        size_t seg = (size_t)p * BTv + b_g;
        int cbase = (tid & 1) * 32;
        #pragma unroll
        for (int cc = 0; cc < 8; cc++) {
            int c0 = cbase + cc * 4;
            float sd = g_s[seg * 8 + (c0 >> 3)] + 1e-9f;
            float inv = 1.f / sd;
            float4 v = *(const float4*)&g_ret[seg * HIDv + c0];
            v.x *= inv; v.y *= inv; v.z *= inv; v.w *= inv;
            v.x = v.x > 0.f ? v.x : expf(v.x) - 1.f;
            v.y = v.y > 0.f ? v.y : expf(v.y) - 1.f;
            v.z = v.z > 0.f ? v.z : expf(v.z) - 1.f;
            v.w = v.w > 0.f ? v.w : expf(v.w) - 1.f;
            *(float4*)&g_ret[seg * HIDv + c0] = v;    // persist for k_final
            uint2 H;
            H.x = pack_bf2(v.x, v.y);
            H.y = pack_bf2(v.z, v.w);
            uint32_t off = (uint32_t)(row * S_LDA + c0) * 2;
            *(uint2*)(sm2 + S_AHI + off) = H;
        }
    }
    __syncthreads();

    int ra   = lane & 15;
    int kadd = (lane >> 4) * 8;
    int nB   = ((lane >> 4) << 3) + (lane & 7);
    int kB   = ((lane >> 3) & 1) * 8;

    float acc[16][4];
    #pragma unroll
    for (int t = 0; t < 16; t++)
        #pragma unroll
        for (int i = 0; i < 4; i++) acc[t][i] = 0.f;

    #pragma unroll
    for (int ks = 0; ks < 4; ks++) {
        uint32_t ahi[4];
        uint32_t aoff = (uint32_t)((wid * 16 + ra) * S_LDA + ks * 16 + kadd) * 2;
        ldsm4(sbase + S_AHI + aoff, ahi);
        #pragma unroll
        for (int ng = 0; ng < 8; ng++) {
            int n = ng * 16 + nB;
            int kp = (ks * 16 + kB) ^ (((n >> 3) & 7) << 3);
            uint32_t boff = (uint32_t)(n * S_LDA + kp) * 2;
            uint32_t bh[4], blo[4];
            ldsm4(sbase + S_BHI + boff, bh);
            ldsm4(sbase + S_BLO + boff, blo);
            mma16816(acc[ng * 2 + 0], ahi, &bh[0]);
            mma16816(acc[ng * 2 + 0], ahi, &blo[0]);
            mma16816(acc[ng * 2 + 1], ahi, &bh[2]);
            mma16816(acc[ng * 2 + 1], ahi, &blo[2]);
        }
    }

    float lsum = 0.f;
    #pragma unroll
    for (int t = 0; t < 16; t++) {
        int col = (t >> 1) * 16 + (t & 1) * 8 + 2 * (lane & 3);
        float bb0 = b1[col], bb1 = b1[col + 1];
        float ww0 = w2[col], ww1 = w2[col + 1];
        lsum += tanhf(acc[t][0] + bb0) * ww0 + tanhf(acc[t][1] + bb1) * ww1
              + tanhf(acc[t][2] + bb0) * ww0 + tanhf(acc[t][3] + bb1) * ww1;
    }
    #pragma unroll
    for (int m = 16; m; m >>= 1) lsum += __shfl_xor_sync(0xffffffffu, lsum, m);
    if (lane == 0) red[wid] = lsum;
    __syncthreads();
    if (tid == 0) {
        float s = 0.f;
        #pragma unroll
        for (int w = 0; w < 8; w++) s += red[w];
        atomicAdd(&g_score[p], s);
    }
}

// -------- final via mma.sync (A bf16, B split): 128x128 per block ------------
__global__ __launch_bounds__(256) void k_final_mma(
    const float* __restrict__ cw1, const float* __restrict__ cb1,
    const float* __restrict__ cw2, float* __restrict__ out)
{
    extern __shared__ __align__(16) char sm3[];
    uint32_t sbase = smem_u32(sm3);
    int tid = threadIdx.x;
    int lane = tid & 31;
    int wid = tid >> 5;

    float s0 = g_score[0] * (1.f / BTv), s1 = g_score[1] * (1.f / BTv);
    float s2 = g_score[2] * (1.f / BTv), s3 = g_score[3] * (1.f / BTv);
    float mu = fmaxf(s0, s1);
    float e0 = __expf(s0 - mu), e1 = __expf(s1 - mu);
    float bu0 = e0 / (e0 + e1), bu1 = e1 / (e0 + e1);
    float mi = fmaxf(s2, s3);
    float e2 = __expf(s2 - mi), e3 = __expf(s3 - mi);
    float bi0 = e2 / (e2 + e3), bi1 = e3 / (e2 + e3);

    #pragma unroll
    for (int it = 0; it < 8; it++) {
        int idx = tid + it * 256;
        int k = idx >> 5;
        int q = (idx & 31) * 4;
        float4 w = *(const float4*)&cw1[(size_t)k * 128 + q];
        float wv[4] = {w.x, w.y, w.z, w.w};
        #pragma unroll
        for (int j = 0; j < 4; j++) {
            int n = q + j;
            int kp = k ^ (((n >> 3) & 7) << 3);
            __nv_bfloat16 h = __float2bfloat16(wv[j]);
            __nv_bfloat16 l = __float2bfloat16(wv[j] - __bfloat162float(h));
            uint32_t off = (uint32_t)(n * S_LDA + kp) * 2;
            *(__nv_bfloat16*)(sm3 + S_BHI + off) = h;
            *(__nv_bfloat16*)(sm3 + S_BLO + off) = l;
        }
    }
    {
        int row = tid >> 1;
        int b_g = blockIdx.x * 128 + row;
        size_t o = (size_t)b_g * HIDv;
        int cbase = (tid & 1) * 32;
        #pragma unroll
        for (int cc = 0; cc < 8; cc++) {
            int c0 = cbase + cc * 4;
            float4 r0 = *(const float4*)&g_ret[o + c0];
            float4 r1 = *(const float4*)&g_ret[(size_t)BTv * HIDv + o + c0];
            float4 r2 = *(const float4*)&g_ret[(size_t)2 * BTv * HIDv + o + c0];
            float4 r3 = *(const float4*)&g_ret[(size_t)3 * BTv * HIDv + o + c0];
            float4 v;
            v.x = (bu0 * r0.x + bu1 * r1.x) * (bi0 * r2.x + bi1 * r3.x);
            v.y = (bu0 * r0.y + bu1 * r1.y) * (bi0 * r2.y + bi1 * r3.y);
            v.z = (bu0 * r0.z + bu1 * r1.z) * (bi0 * r2.z + bi1 * r3.z);
            v.w = (bu0 * r0.w + bu1 * r1.w) * (bi0 * r2.w + bi1 * r3.w);
            uint2 H;
            H.x = pack_bf2(v.x, v.y);
            H.y = pack_bf2(v.z, v.w);
            uint32_t off = (uint32_t)(row * S_LDA + c0) * 2;
            *(uint2*)(sm3 + S_AHI + off) = H;
        }
    }
    __syncthreads();

    int ra   = lane & 15;
    int kadd = (lane >> 4) * 8;
    int nB   = ((lane >> 4) << 3) + (lane & 7);
    int kB   = ((lane >> 3) & 1) * 8;

    float acc[16][4];
    #pragma unroll
    for (int t = 0; t < 16; t++)
        #pragma unroll
        for (int i = 0; i < 4; i++) acc[t][i] = 0.f;

    #pragma unroll
    for (int ks = 0; ks < 4; ks++) {
        uint32_t ahi[4];
        uint32_t aoff = (uint32_t)((wid * 16 + ra) * S_LDA + ks * 16 + kadd) * 2;
        ldsm4(sbase + S_AHI + aoff, ahi);
        #pragma unroll
        for (int ng = 0; ng < 8; ng++) {
            int n = ng * 16 + nB;
            int kp = (ks * 16 + kB) ^ (((n >> 3) & 7) << 3);
            uint32_t boff = (uint32_t)(n * S_LDA + kp) * 2;
            uint32_t bh[4], blo[4];
            ldsm4(sbase + S_BHI + boff, bh);
            ldsm4(sbase + S_BLO + boff, blo);
            mma16816(acc[ng * 2 + 0], ahi, &bh[0]);
            mma16816(acc[ng * 2 + 0], ahi, &blo[0]);
            mma16816(acc[ng * 2 + 1], ahi, &bh[2]);
            mma16816(acc[ng * 2 + 1], ahi, &blo[2]);
        }
    }

    float l0a = 0.f, l1a = 0.f, l0b = 0.f, l1b = 0.f;
    #pragma unroll
    for (int t = 0; t < 16; t++) {
        int col = (t >> 1) * 16 + (t & 1) * 8 + 2 * (lane & 3);
        float bb0 = cb1[col], bb1 = cb1[col + 1];
        float wa0 = cw2[col * 2 + 0],       wb0 = cw2[col * 2 + 1];
        float wa1 = cw2[(col + 1) * 2 + 0], wb1 = cw2[(col + 1) * 2 + 1];
        float h;
        h = fmaxf(acc[t][0] + bb0, 0.f); l0a += h * wa0; l1a += h * wb0;
        h = fmaxf(acc[t][1] + bb1, 0.f); l0a += h * wa1; l1a += h * wb1;
        h = fmaxf(acc[t][2] + bb0, 0.f); l0b += h * wa0; l1b += h * wb0;
        h = fmaxf(acc[t][3] + bb1, 0.f); l0b += h * wa1; l1b += h * wb1;
    }
    #pragma unroll
    for (int m = 1; m < 4; m <<= 1) {
        l0a += __shfl_xor_sync(0xffffffffu, l0a, m);
        l1a += __shfl_xor_sync(0xffffffffu, l1a, m);
        l0b += __shfl_xor_sync(0xffffffffu, l0b, m);
        l1b += __shfl_xor_sync(0xffffffffu, l1b, m);
    }
    if ((lane & 3) == 0) {
        int r0 = blockIdx.x * 128 + wid * 16 + (lane >> 2);
        float mm = fmaxf(l0a, l1a);
        float ea = __expf(l0a - mm), eb = __expf(l1a - mm);
        float inv = 1.f / (ea + eb);
        out[r0 * 2 + 0] = ea * inv;
        out[r0 * 2 + 1] = eb * inv;
        int r1 = r0 + 8;
        mm = fmaxf(l0b, l1b);
        ea = __expf(l0b - mm); eb = __expf(l1b - mm);
        inv = 1.f / (ea + eb);
        out[r1 * 2 + 0] = ea * inv;
        out[r1 * 2 + 1] = eb * inv;
    }
}

// -----------------------------------------------------------------------------
extern "C" void kernel_launch(void* const* d_in, const int* in_sizes, int n_in,
                              void* d_out, int out_size)
{
    const float* feats0 = (const float*)d_in[0];
    const float* feats1 = (const float*)d_in[1];
    const float* t0_pw  = (const float*)d_in[2];
    const float* t0_pb  = (const float*)d_in[3];
    const float* t0_w2  = (const float*)d_in[4];
    const float* t0_b2  = (const float*)d_in[5];
    const float* t0_g   = (const float*)d_in[6];
    const float* t0_be  = (const float*)d_in[7];
    const float* t1_pw  = (const float*)d_in[8];
    const float* t1_pb  = (const float*)d_in[9];
    const float* t1_w2  = (const float*)d_in[10];
    const float* t1_b2  = (const float*)d_in[11];
    const float* t1_g   = (const float*)d_in[12];
    const float* t1_be  = (const float*)d_in[13];
    const float* r_vec  = (const float*)d_in[14];
    const float* attn_u = (const float*)d_in[15];
    const float* attn_i = (const float*)d_in[16];
    const float* su_w1  = (const float*)d_in[17];
    const float* su_b1  = (const float*)d_in[18];
    const float* su_w2  = (const float*)d_in[19];
    const float* si_w1  = (const float*)d_in[20];
    const float* si_b1  = (const float*)d_in[21];
    const float* si_w2  = (const float*)d_in[22];
    const float* cw1    = (const float*)d_in[23];
    const float* cb1    = (const float*)d_in[24];
    const float* cw2    = (const float*)d_in[25];
    const int*   idx0   = (const int*)d_in[26];
    const int*   idx1   = (const int*)d_in[27];
    const int*   emi_u  = (const int*)d_in[28];
    const int*   tgt_u  = (const int*)d_in[29];
    const int*   emi_i  = (const int*)d_in[30];
    const int*   tgt_i  = (const int*)d_in[31];

    static int smem_set = 0;
    if (!smem_set) {
        cudaFuncSetAttribute(k_tower_mma, cudaFuncAttributeMaxDynamicSharedMemorySize, SMTOT);
        cudaFuncSetAttribute(k_sem_mma, cudaFuncAttributeMaxDynamicSharedMemorySize, S_TOT);
        cudaFuncSetAttribute(k_final_mma, cudaFuncAttributeMaxDynamicSharedMemorySize, S_TOT);
        smem_set = 1;
    }

    int NBT = (N0v + 127) / 128 + (N1v + 127) / 128;
    k_tower_mma<<<NBT, 256, SMTOT>>>(feats0, feats1,
        t0_pw, t0_pb, t0_w2, t0_b2, t0_g, t0_be,
        t1_pw, t1_pb, t1_w2, t1_b2, t1_g, t1_be, idx0, idx1, r_vec);
    k_mpf<<<NPv * EPM / 16, 256>>>(emi_u, tgt_u, emi_i, tgt_i, attn_u, attn_i);
    dim3 gsem(BTv / 128, NPv);
    k_sem_mma<<<gsem, 256, S_TOT>>>(su_w1, su_b1, su_w2, si_w1, si_b1, si_w2);
    k_final_mma<<<BTv / 128, 256, S_TOT>>>(cw1, cb1, cw2, (float*)d_out);
}

// round 13
// speedup vs baseline: 1.0569x; 1.0569x over previous
#include <cuda_runtime.h>
#include <cuda_bf16.h>
#include <math.h>
#include <stdint.h>

#define N0v 20000
#define N1v 20000
#define NNODE 40000
#define F0v 512
#define HIDv 64
#define EPM 200000
#define BTv 8192
#define NPv 4

// ---------------- scratch (static device globals; no allocation) -------------
__device__ __align__(16) float g_feat[NNODE * HIDv];     // 10.24 MB
__device__ __align__(16) float g_s[NPv * BTv * 8];       // seg sum of exp(e)
__device__ __align__(16) float g_ret[NPv * BTv * HIDv];  // seg sum of exp(e)*eft
__device__ __align__(16) float g_fr[2 * 3 * 64];         // [side][l][k-pair re/im]
__device__ float g_score[4];

// ================= mma.sync helpers (arch-neutral HMMA path) ================
__device__ __forceinline__ uint32_t smem_u32(const void* p) {
    uint32_t a;
    asm("{ .reg .u64 t; cvta.to.shared.u64 t, %1; cvt.u32.u64 %0, t; }" : "=r"(a) : "l"(p));
    return a;
}
__device__ __forceinline__ void ldsm4(uint32_t addr, uint32_t* r) {
    asm volatile("ldmatrix.sync.aligned.m8n8.x4.shared.b16 {%0,%1,%2,%3}, [%4];"
        : "=r"(r[0]), "=r"(r[1]), "=r"(r[2]), "=r"(r[3]) : "r"(addr));
}
__device__ __forceinline__ void mma16816(float* d, const uint32_t* a, const uint32_t* b) {
    asm volatile(
        "mma.sync.aligned.m16n8k16.row.col.f32.bf16.bf16.f32 "
        "{%0,%1,%2,%3}, {%4,%5,%6,%7}, {%8,%9}, {%0,%1,%2,%3};"
        : "+f"(d[0]), "+f"(d[1]), "+f"(d[2]), "+f"(d[3])
        : "r"(a[0]), "r"(a[1]), "r"(a[2]), "r"(a[3]), "r"(b[0]), "r"(b[1]));
}
__device__ __forceinline__ void split2(float a, float b, uint32_t& hi, uint32_t& lo) {
    __nv_bfloat16 ha = __float2bfloat16(a), hb = __float2bfloat16(b);
    __nv_bfloat16 la = __float2bfloat16(a - __bfloat162float(ha));
    __nv_bfloat16 lb = __float2bfloat16(b - __bfloat162float(hb));
    hi = ((uint32_t)__bfloat16_as_ushort(hb) << 16) | (uint32_t)__bfloat16_as_ushort(ha);
    lo = ((uint32_t)__bfloat16_as_ushort(lb) << 16) | (uint32_t)__bfloat16_as_ushort(la);
}

#define LDA 72          // bf16 elems per smem row (144 B = 9*16, ldmatrix-legal)
#define OF_AHI 0        // A hi: 128 x 72 bf16 = 18432 B
#define OF_ALO 18432    // A lo
#define OF_BHI 36864    // B hi: 64 x 72 bf16 = 9216 B
#define OF_BLO 46080    // B lo
#define SMTOT  55296

// ------- tower via mma.sync bf16 split + fused init: 128 nodes / block -------
__global__ __launch_bounds__(256) void k_tower_mma(
    const float* __restrict__ feats0, const float* __restrict__ feats1,
    const float* __restrict__ pw0, const float* __restrict__ pb0,
    const float* __restrict__ w20, const float* __restrict__ b20,
    const float* __restrict__ gg0, const float* __restrict__ be0,
    const float* __restrict__ pw1, const float* __restrict__ pb1,
    const float* __restrict__ w21, const float* __restrict__ b21,
    const float* __restrict__ gg1, const float* __restrict__ be1,
    const int* __restrict__ idx0, const int* __restrict__ idx1,
    const float* __restrict__ r_vec)
{
    extern __shared__ __align__(16) char sm[];
    uint32_t sbase = smem_u32(sm);
    int tid = threadIdx.x;
    int lane = tid & 31;
    int wid = tid >> 5;

    // ---- fused init: zero accumulators (grid-strided), g_fr on block 0 ------
    {
        int gt = blockIdx.x * 256 + tid;
        int gstride = gridDim.x * 256;
        float4 z4 = make_float4(0.f, 0.f, 0.f, 0.f);
        for (int i = gt; i < NPv * BTv * HIDv / 4; i += gstride)
            ((float4*)g_ret)[i] = z4;
        for (int i = gt; i < NPv * BTv * 8 / 4; i += gstride)
            ((float4*)g_s)[i] = z4;
        if (blockIdx.x == 0) {
            if (tid < 4) g_score[tid] = 0.f;
            if (tid < 32) {
                int k = tid;
                float rr = r_vec[k * 2 + 0], ri = r_vec[k * 2 + 1];
                float nm = sqrtf(rr * rr + ri * ri);
                float cr = rr / nm, ci = ri / nm;
                float u1r = cr,  u1i = -ci;
                float u0r = u1r * cr - u1i * ci;
                float u0i = u1r * ci + u1i * cr;
                g_fr[(0 * 3 + 0) * 64 + 2 * k] = u0r; g_fr[(0 * 3 + 0) * 64 + 2 * k + 1] = u0i;
                g_fr[(0 * 3 + 1) * 64 + 2 * k] = u1r; g_fr[(0 * 3 + 1) * 64 + 2 * k + 1] = u1i;
                g_fr[(0 * 3 + 2) * 64 + 2 * k] = 1.f; g_fr[(0 * 3 + 2) * 64 + 2 * k + 1] = 0.f;
                float i1r = cr,  i1i = ci;
                float i0r = i1r * cr - i1i * (-ci);
                float i0i = i1r * (-ci) + i1i * cr;
                g_fr[(1 * 3 + 0) * 64 + 2 * k] = i0r; g_fr[(1 * 3 + 0) * 64 + 2 * k + 1] = i0i;
                g_fr[(1 * 3 + 1) * 64 + 2 * k] = i1r; g_fr[(1 * 3 + 1) * 64 + 2 * k + 1] = i1i;
                g_fr[(1 * 3 + 2) * 64 + 2 * k] = 1.f; g_fr[(1 * 3 + 2) * 64 + 2 * k + 1] = 0.f;
            }
        }
    }

    const int NB0 = (N0v + 127) / 128;
    int bt = blockIdx.x;
    int tower = (bt >= NB0) ? 1 : 0;
    int bl = tower ? bt - NB0 : bt;
    int nbase = bl * 128;
    int Nlim = tower ? N1v : N0v;
    int valid = Nlim - nbase; if (valid > 128) valid = 128;
    const float* X  = tower ? feats1 : feats0;
    const float* PW = tower ? pw1 : pw0;
    const float* PB = tower ? pb1 : pb0;
    const float* W2 = tower ? w21 : w20;
    const float* B2 = tower ? b21 : b20;
    const float* GG = tower ? gg1 : gg0;
    const float* BE = tower ? be1 : be0;
    const int*  IDX = tower ? idx1 : idx0;

    int ra    = lane & 15;
    int kadd  = (lane >> 4) * 8;
    int nB    = ((lane >> 4) << 3) + (lane & 7);
    int kB    = ((lane >> 3) & 1) * 8;

    float acc[8][4];
    #pragma unroll
    for (int nt = 0; nt < 8; nt++)
        #pragma unroll
        for (int i = 0; i < 4; i++) acc[nt][i] = 0.f;

    // loader geometry (constant across chunks)
    int ldrow = tid >> 4;              // two rows per thread via +it strides
    int ldq   = tid & 15;
    int gr_base;
    {
        int gr = nbase + ldrow; if (gr >= Nlim) gr = Nlim - 1;  // row for it=0 pattern
        gr_base = gr;                                            // recomputed per it below
    }
    (void)gr_base;

    // =================== GEMM1: X[128x512] @ W1[512x64] ======================
    // software pipeline: prefetch next chunk's A (DRAM-streamed) during MMA
    float4 xf[8];
    #pragma unroll
    for (int it = 0; it < 8; it++) {
        int idx = tid + it * 256;
        int row = idx >> 4, q = idx & 15;
        int gr = nbase + row; if (gr >= Nlim) gr = Nlim - 1;
        xf[it] = *(const float4*)&X[(size_t)gr * F0v + q * 4];
    }
    for (int c = 0; c < 8; c++) {
        // store current A chunk from registers (convert to bf16 hi/lo)
        #pragma unroll
        for (int it = 0; it < 8; it++) {
            int idx = tid + it * 256;
            int row = idx >> 4, q = idx & 15;
            uint2 H, L;
            split2(xf[it].x, xf[it].y, H.x, L.x);
            split2(xf[it].z, xf[it].w, H.y, L.y);
            uint32_t off = (uint32_t)(row * LDA + q * 4) * 2;
            *(uint2*)(sm + OF_AHI + off) = H;
            *(uint2*)(sm + OF_ALO + off) = L;
        }
        // B chunk (L2-hot weights)
        #pragma unroll
        for (int it = 0; it < 4; it++) {
            int idx = tid + it * 256;
            int k = idx >> 4, q = (idx & 15) * 4;
            float4 w = *(const float4*)&PW[(size_t)(c * 64 + k) * HIDv + q];
            float wv[4] = {w.x, w.y, w.z, w.w};
            #pragma unroll
            for (int j = 0; j < 4; j++) {
                int n = q + j;
                int kp = k ^ (((n >> 3) & 7) << 3);
                __nv_bfloat16 h = __float2bfloat16(wv[j]);
                __nv_bfloat16 l = __float2bfloat16(wv[j] - __bfloat162float(h));
                uint32_t off = (uint32_t)(n * LDA + kp) * 2;
                *(__nv_bfloat16*)(sm + OF_BHI + off) = h;
                *(__nv_bfloat16*)(sm + OF_BLO + off) = l;
            }
        }
        __syncthreads();
        // prefetch next A chunk: LDG latency hides under the MMA phase below
        if (c < 7) {
            #pragma unroll
            for (int it = 0; it < 8; it++) {
                int idx = tid + it * 256;
                int row = idx >> 4, q = idx & 15;
                int gr = nbase + row; if (gr >= Nlim) gr = Nlim - 1;
                xf[it] = *(const float4*)&X[(size_t)gr * F0v + (c + 1) * 64 + q * 4];
            }
        }
        #pragma unroll
        for (int ks = 0; ks < 4; ks++) {
            uint32_t ahi[4], alo[4], bh[16], blo[16];
            uint32_t aoff = (uint32_t)((wid * 16 + ra) * LDA + ks * 16 + kadd) * 2;
            ldsm4(sbase + OF_AHI + aoff, ahi);
            ldsm4(sbase + OF_ALO + aoff, alo);
            #pragma unroll
            for (int ng = 0; ng < 4; ng++) {
                int n = ng * 16 + nB;
                int kp = (ks * 16 + kB) ^ (((n >> 3) & 7) << 3);
                uint32_t boff = (uint32_t)(n * LDA + kp) * 2;
                ldsm4(sbase + OF_BHI + boff, &bh[ng * 4]);
                ldsm4(sbase + OF_BLO + boff, &blo[ng * 4]);
            }
            #pragma unroll
            for (int nt = 0; nt < 8; nt++) {
                mma16816(acc[nt], ahi, &bh[nt * 2]);
                mma16816(acc[nt], ahi, &blo[nt * 2]);
                mma16816(acc[nt], alo, &bh[nt * 2]);
            }
        }
        __syncthreads();
    }

    // =================== z = acc + b1; h = gelu(z) -> A smem =================
    int nlo = 2 * (lane & 3);
    int r0 = wid * 16 + (lane >> 2);
    int r1 = r0 + 8;
    float z[8][4];
    #pragma unroll
    for (int nt = 0; nt < 8; nt++) {
        float b0 = PB[nt * 8 + nlo], b1v = PB[nt * 8 + nlo + 1];
        z[nt][0] = acc[nt][0] + b0;  z[nt][1] = acc[nt][1] + b1v;
        z[nt][2] = acc[nt][2] + b0;  z[nt][3] = acc[nt][3] + b1v;
        float h0 = 0.5f * z[nt][0] * (1.f + erff(z[nt][0] * 0.70710678118654752f));
        float h1 = 0.5f * z[nt][1] * (1.f + erff(z[nt][1] * 0.70710678118654752f));
        float h2 = 0.5f * z[nt][2] * (1.f + erff(z[nt][2] * 0.70710678118654752f));
        float h3 = 0.5f * z[nt][3] * (1.f + erff(z[nt][3] * 0.70710678118654752f));
        uint32_t H01, L01, H23, L23;
        split2(h0, h1, H01, L01);
        split2(h2, h3, H23, L23);
        uint32_t o0 = (uint32_t)(r0 * LDA + nt * 8 + nlo) * 2;
        uint32_t o1 = (uint32_t)(r1 * LDA + nt * 8 + nlo) * 2;
        *(uint32_t*)(sm + OF_AHI + o0) = H01;
        *(uint32_t*)(sm + OF_ALO + o0) = L01;
        *(uint32_t*)(sm + OF_AHI + o1) = H23;
        *(uint32_t*)(sm + OF_ALO + o1) = L23;
        acc[nt][0] = 0.f; acc[nt][1] = 0.f; acc[nt][2] = 0.f; acc[nt][3] = 0.f;
    }
    #pragma unroll
    for (int it = 0; it < 4; it++) {
        int idx = tid + it * 256;
        int k = idx >> 4, q = (idx & 15) * 4;
        float4 w = *(const float4*)&W2[(size_t)k * HIDv + q];
        float wv[4] = {w.x, w.y, w.z, w.w};
        #pragma unroll
        for (int j = 0; j < 4; j++) {
            int n = q + j;
            int kp = k ^ (((n >> 3) & 7) << 3);
            __nv_bfloat16 h = __float2bfloat16(wv[j]);
            __nv_bfloat16 l = __float2bfloat16(wv[j] - __bfloat162float(h));
            uint32_t off = (uint32_t)(n * LDA + kp) * 2;
            *(__nv_bfloat16*)(sm + OF_BHI + off) = h;
            *(__nv_bfloat16*)(sm + OF_BLO + off) = l;
        }
    }
    __syncthreads();

    // =================== GEMM2: h[128x64] @ W2[64x64] ========================
    #pragma unroll
    for (int ks = 0; ks < 4; ks++) {
        uint32_t ahi[4], alo[4], bh[16], blo[16];
        uint32_t aoff = (uint32_t)((wid * 16 + ra) * LDA + ks * 16 + kadd) * 2;
        ldsm4(sbase + OF_AHI + aoff, ahi);
        ldsm4(sbase + OF_ALO + aoff, alo);
        #pragma unroll
        for (int ng = 0; ng < 4; ng++) {
            int n = ng * 16 + nB;
            int kp = (ks * 16 + kB) ^ (((n >> 3) & 7) << 3);
            uint32_t boff = (uint32_t)(n * LDA + kp) * 2;
            ldsm4(sbase + OF_BHI + boff, &bh[ng * 4]);
            ldsm4(sbase + OF_BLO + boff, &blo[ng * 4]);
        }
        #pragma unroll
        for (int nt = 0; nt < 8; nt++) {
            mma16816(acc[nt], ahi, &bh[nt * 2]);
            mma16816(acc[nt], ahi, &blo[nt * 2]);
            mma16816(acc[nt], alo, &bh[nt * 2]);
        }
    }

    // =================== y = acc + b2 + z; LayerNorm; store ==================
    float y[8][4];
    float s1a = 0.f, s2a = 0.f, s1b = 0.f, s2b = 0.f;
    #pragma unroll
    for (int nt = 0; nt < 8; nt++) {
        float b0 = B2[nt * 8 + nlo], b1v = B2[nt * 8 + nlo + 1];
        y[nt][0] = acc[nt][0] + b0 + z[nt][0];
        y[nt][1] = acc[nt][1] + b1v + z[nt][1];
        y[nt][2] = acc[nt][2] + b0 + z[nt][2];
        y[nt][3] = acc[nt][3] + b1v + z[nt][3];
        s1a += y[nt][0] + y[nt][1];
        s2a += y[nt][0] * y[nt][0] + y[nt][1] * y[nt][1];
        s1b += y[nt][2] + y[nt][3];
        s2b += y[nt][2] * y[nt][2] + y[nt][3] * y[nt][3];
    }
    #pragma unroll
    for (int m = 1; m < 4; m <<= 1) {
        s1a += __shfl_xor_sync(0xffffffffu, s1a, m);
        s2a += __shfl_xor_sync(0xffffffffu, s2a, m);
        s1b += __shfl_xor_sync(0xffffffffu, s1b, m);
        s2b += __shfl_xor_sync(0xffffffffu, s2b, m);
    }
    float mu0 = s1a * (1.f / 64.f);
    float rs0 = rsqrtf(s2a * (1.f / 64.f) - mu0 * mu0 + 1e-5f);
    float mu1 = s1b * (1.f / 64.f);
    float rs1 = rsqrtf(s2b * (1.f / 64.f) - mu1 * mu1 + 1e-5f);
    if (r0 < valid) {
        int gn = IDX[nbase + r0];
        #pragma unroll
        for (int nt = 0; nt < 8; nt++) {
            float2 o;
            o.x = (y[nt][0] - mu0) * rs0 * GG[nt * 8 + nlo] + BE[nt * 8 + nlo];
            o.y = (y[nt][1] - mu0) * rs0 * GG[nt * 8 + nlo + 1] + BE[nt * 8 + nlo + 1];
            *(float2*)&g_feat[(size_t)gn * HIDv + nt * 8 + nlo] = o;
        }
    }
    if (r1 < valid) {
        int gn = IDX[nbase + r1];
        #pragma unroll
        for (int nt = 0; nt < 8; nt++) {
            float2 o;
            o.x = (y[nt][2] - mu1) * rs1 * GG[nt * 8 + nlo] + BE[nt * 8 + nlo];
            o.y = (y[nt][3] - mu1) * rs1 * GG[nt * 8 + nlo + 1] + BE[nt * 8 + nlo + 1];
            *(float2*)&g_feat[(size_t)gn * HIDv + nt * 8 + nlo] = o;
        }
    }
}

// ---- fused metapath: gather+rotate+mean -> e -> exp -> seg sums (no max) ----
__global__ __launch_bounds__(256) void k_mpf(
    const int* __restrict__ emi_u, const int* __restrict__ tgt_u,
    const int* __restrict__ emi_i, const int* __restrict__ tgt_i,
    const float* __restrict__ attn_u, const float* __restrict__ attn_i)
{
    int warp = blockIdx.x * (blockDim.x >> 5) + (threadIdx.x >> 5);
    int lane = threadIdx.x & 31;
    int half = lane >> 4;
    int sl = lane & 15;
    int inst = warp * 2 + half;
    int p = inst / EPM;
    int i = inst - p * EPM;
    int side = p >> 1, pl = p & 1;
    const int* emi = side ? emi_i : emi_u;
    const int* tgt = side ? tgt_i : tgt_u;
    const float* attn = side ? attn_i : attn_u;

    int n = 0;
    if (sl < 3) n = emi[((size_t)pl * EPM + i) * 3 + sl];
    float re0 = 0.f, im0 = 0.f, re1 = 0.f, im1 = 0.f;
    #pragma unroll
    for (int l = 0; l < 3; l++) {
        int nl = __shfl_sync(0xffffffffu, n, half * 16 + l);
        float4 v  = *(const float4*)&g_feat[(size_t)nl * HIDv + sl * 4];
        float4 fr = *(const float4*)&g_fr[(side * 3 + l) * 64 + sl * 4];
        re0 += v.x * fr.x - v.y * fr.y;
        im0 += v.x * fr.y + v.y * fr.x;
        re1 += v.z * fr.z - v.w * fr.w;
        im1 += v.z * fr.w + v.w * fr.z;
    }
    re0 *= (1.f / 3.f); im0 *= (1.f / 3.f);
    re1 *= (1.f / 3.f); im1 *= (1.f / 3.f);

    int h = sl >> 1;
    int dpart = (sl & 1) * 4;
    float4 av = *(const float4*)&attn[(pl * 8 + h) * 8 + dpart];
    float ep = re0 * av.x + im0 * av.y + re1 * av.z + im1 * av.w;
    ep += __shfl_xor_sync(0xffffffffu, ep, 1);
    float ev = ep > 0.f ? ep : 0.01f * ep;
    float a = __expf(ev);

    int t = tgt[(size_t)pl * EPM + i];
    size_t seg = (size_t)p * BTv + t;
    if ((sl & 1) == 0) atomicAdd(&g_s[seg * 8 + h], a);
    atomicAdd((float4*)&g_ret[seg * HIDv + sl * 4],
              make_float4(a * re0, a * im0, a * re1, a * im1));
}

// -------- semantic via mma.sync: 128 rows x 128 cols per block ---------------
#define S_LDA 72
#define S_AHI 0
#define S_ALO 18432
#define S_BHI 36864
#define S_BLO 55296
#define S_TOT 73728

__global__ __launch_bounds__(256) void k_sem_mma(
    const float* __restrict__ su_w1, const float* __restrict__ su_b1, const float* __restrict__ su_w2,
    const float* __restrict__ si_w1, const float* __restrict__ si_b1, const float* __restrict__ si_w2)
{
    extern __shared__ __align__(16) char sm2[];
    uint32_t sbase = smem_u32(sm2);
    __shared__ float red[8];
    int p = blockIdx.y;
    const float* w1 = (p < 2) ? su_w1 : si_w1;
    const float* b1 = (p < 2) ? su_b1 : si_b1;
    const float* w2 = (p < 2) ? su_w2 : si_w2;
    int tid = threadIdx.x;
    int lane = tid & 31;
    int wid = tid >> 5;

    #pragma unroll
    for (int it = 0; it < 8; it++) {
        int idx = tid + it * 256;
        int k = idx >> 5;
        int q = (idx & 31) * 4;
        float4 w = *(const float4*)&w1[(size_t)k * 128 + q];
        float wv[4] = {w.x, w.y, w.z, w.w};
        #pragma unroll
        for (int j = 0; j < 4; j++) {
            int n = q + j;
            int kp = k ^ (((n >> 3) & 7) << 3);
            __nv_bfloat16 h = __float2bfloat16(wv[j]);
            __nv_bfloat16 l = __float2bfloat16(wv[j] - __bfloat162float(h));
            uint32_t off = (uint32_t)(n * S_LDA + kp) * 2;
            *(__nv_bfloat16*)(sm2 + S_BHI + off) = h;
            *(__nv_bfloat16*)(sm2 + S_BLO + off) = l;
        }
    }
    {
        int row = tid >> 1;
        int b_g = blockIdx.x * 128 + row;
        size_t seg = (size_t)p * BTv + b_g;
        int cbase = (tid & 1) * 32;
        #pragma unroll
        for (int cc = 0; cc < 8; cc++) {
            int c0 = cbase + cc * 4;
            float sd = g_s[seg * 8 + (c0 >> 3)] + 1e-9f;
            float inv = 1.f / sd;
            float4 v = *(const float4*)&g_ret[seg * HIDv + c0];
            v.x *= inv; v.y *= inv; v.z *= inv; v.w *= inv;
            v.x = v.x > 0.f ? v.x : expf(v.x) - 1.f;
            v.y = v.y > 0.f ? v.y : expf(v.y) - 1.f;
            v.z = v.z > 0.f ? v.z : expf(v.z) - 1.f;
            v.w = v.w > 0.f ? v.w : expf(v.w) - 1.f;
            *(float4*)&g_ret[seg * HIDv + c0] = v;    // persist for k_final
            uint2 H, L;
            split2(v.x, v.y, H.x, L.x);
            split2(v.z, v.w, H.y, L.y);
            uint32_t off = (uint32_t)(row * S_LDA + c0) * 2;
            *(uint2*)(sm2 + S_AHI + off) = H;
            *(uint2*)(sm2 + S_ALO + off) = L;
        }
    }
    __syncthreads();

    int ra   = lane & 15;
    int kadd = (lane >> 4) * 8;
    int nB   = ((lane >> 4) << 3) + (lane & 7);
    int kB   = ((lane >> 3) & 1) * 8;

    float acc[16][4];
    #pragma unroll
    for (int t = 0; t < 16; t++)
        #pragma unroll
        for (int i = 0; i < 4; i++) acc[t][i] = 0.f;

    #pragma unroll
    for (int ks = 0; ks < 4; ks++) {
        uint32_t ahi[4], alo[4];
        uint32_t aoff = (uint32_t)((wid * 16 + ra) * S_LDA + ks * 16 + kadd) * 2;
        ldsm4(sbase + S_AHI + aoff, ahi);
        ldsm4(sbase + S_ALO + aoff, alo);
        #pragma unroll
        for (int ng = 0; ng < 8; ng++) {
            int n = ng * 16 + nB;
            int kp = (ks * 16 + kB) ^ (((n >> 3) & 7) << 3);
            uint32_t boff = (uint32_t)(n * S_LDA + kp) * 2;
            uint32_t bh[4], blo[4];
            ldsm4(sbase + S_BHI + boff, bh);
            ldsm4(sbase + S_BLO + boff, blo);
            mma16816(acc[ng * 2 + 0], ahi, &bh[0]);
            mma16816(acc[ng * 2 + 0], ahi, &blo[0]);
            mma16816(acc[ng * 2 + 0], alo, &bh[0]);
            mma16816(acc[ng * 2 + 1], ahi, &bh[2]);
            mma16816(acc[ng * 2 + 1], ahi, &blo[2]);
            mma16816(acc[ng * 2 + 1], alo, &bh[2]);
        }
    }

    float lsum = 0.f;
    #pragma unroll
    for (int t = 0; t < 16; t++) {
        int col = (t >> 1) * 16 + (t & 1) * 8 + 2 * (lane & 3);
        float bb0 = b1[col], bb1 = b1[col + 1];
        float ww0 = w2[col], ww1 = w2[col + 1];
        lsum += tanhf(acc[t][0] + bb0) * ww0 + tanhf(acc[t][1] + bb1) * ww1
              + tanhf(acc[t][2] + bb0) * ww0 + tanhf(acc[t][3] + bb1) * ww1;
    }
    #pragma unroll
    for (int m = 16; m; m >>= 1) lsum += __shfl_xor_sync(0xffffffffu, lsum, m);
    if (lane == 0) red[wid] = lsum;
    __syncthreads();
    if (tid == 0) {
        float s = 0.f;
        #pragma unroll
        for (int w = 0; w < 8; w++) s += red[w];
        atomicAdd(&g_score[p], s);
    }
}

// -------- final via mma.sync: 128 rows x 128 cols per block ------------------
__global__ __launch_bounds__(256) void k_final_mma(
    const float* __restrict__ cw1, const float* __restrict__ cb1,
    const float* __restrict__ cw2, float* __restrict__ out)
{
    extern __shared__ __align__(16) char sm3[];
    uint32_t sbase = smem_u32(sm3);
    int tid = threadIdx.x;
    int lane = tid & 31;
    int wid = tid >> 5;

    float s0 = g_score[0] * (1.f / BTv), s1 = g_score[1] * (1.f / BTv);
    float s2 = g_score[2] * (1.f / BTv), s3 = g_score[3] * (1.f / BTv);
    float mu = fmaxf(s0, s1);
    float e0 = __expf(s0 - mu), e1 = __expf(s1 - mu);
    float bu0 = e0 / (e0 + e1), bu1 = e1 / (e0 + e1);
    float mi = fmaxf(s2, s3);
    float e2 = __expf(s2 - mi), e3 = __expf(s3 - mi);
    float bi0 = e2 / (e2 + e3), bi1 = e3 / (e2 + e3);

    // cw1[64k x 128n] -> B smem [n][k^swz] bf16 hi/lo
    #pragma unroll
    for (int it = 0; it < 8; it++) {
        int idx = tid + it * 256;
        int k = idx >> 5;
        int q = (idx & 31) * 4;
        float4 w = *(const float4*)&cw1[(size_t)k * 128 + q];
        float wv[4] = {w.x, w.y, w.z, w.w};
        #pragma unroll
        for (int j = 0; j < 4; j++) {
            int n = q + j;
            int kp = k ^ (((n >> 3) & 7) << 3);
            __nv_bfloat16 h = __float2bfloat16(wv[j]);
            __nv_bfloat16 l = __float2bfloat16(wv[j] - __bfloat162float(h));
            uint32_t off = (uint32_t)(n * S_LDA + kp) * 2;
            *(__nv_bfloat16*)(sm3 + S_BHI + off) = h;
            *(__nv_bfloat16*)(sm3 + S_BLO + off) = l;
        }
    }
    // rows: beta-combine + product -> A smem bf16 hi/lo
    {
        int row = tid >> 1;
        int b_g = blockIdx.x * 128 + row;
        size_t o = (size_t)b_g * HIDv;
        int cbase = (tid & 1) * 32;
        #pragma unroll
        for (int cc = 0; cc < 8; cc++) {
            int c0 = cbase + cc * 4;
            float4 r0 = *(const float4*)&g_ret[o + c0];
            float4 r1 = *(const float4*)&g_ret[(size_t)BTv * HIDv + o + c0];
            float4 r2 = *(const float4*)&g_ret[(size_t)2 * BTv * HIDv + o + c0];
            float4 r3 = *(const float4*)&g_ret[(size_t)3 * BTv * HIDv + o + c0];
            float4 v;
            v.x = (bu0 * r0.x + bu1 * r1.x) * (bi0 * r2.x + bi1 * r3.x);
            v.y = (bu0 * r0.y + bu1 * r1.y) * (bi0 * r2.y + bi1 * r3.y);
            v.z = (bu0 * r0.z + bu1 * r1.z) * (bi0 * r2.z + bi1 * r3.z);
            v.w = (bu0 * r0.w + bu1 * r1.w) * (bi0 * r2.w + bi1 * r3.w);
            uint2 H, L;
            split2(v.x, v.y, H.x, L.x);
            split2(v.z, v.w, H.y, L.y);
            uint32_t off = (uint32_t)(row * S_LDA + c0) * 2;
            *(uint2*)(sm3 + S_AHI + off) = H;
            *(uint2*)(sm3 + S_ALO + off) = L;
        }
    }
    __syncthreads();

    int ra   = lane & 15;
    int kadd = (lane >> 4) * 8;
    int nB   = ((lane >> 4) << 3) + (lane & 7);
    int kB   = ((lane >> 3) & 1) * 8;

    float acc[16][4];
    #pragma unroll
    for (int t = 0; t < 16; t++)
        #pragma unroll
        for (int i = 0; i < 4; i++) acc[t][i] = 0.f;

    #pragma unroll
    for (int ks = 0; ks < 4; ks++) {
        uint32_t ahi[4], alo[4];
        uint32_t aoff = (uint32_t)((wid * 16 + ra) * S_LDA + ks * 16 + kadd) * 2;
        ldsm4(sbase + S_AHI + aoff, ahi);
        ldsm4(sbase + S_ALO + aoff, alo);
        #pragma unroll
        for (int ng = 0; ng < 8; ng++) {
            int n = ng * 16 + nB;
            int kp = (ks * 16 + kB) ^ (((n >> 3) & 7) << 3);
            uint32_t boff = (uint32_t)(n * S_LDA + kp) * 2;
            uint32_t bh[4], blo[4];
            ldsm4(sbase + S_BHI + boff, bh);
            ldsm4(sbase + S_BLO + boff, blo);
            mma16816(acc[ng * 2 + 0], ahi, &bh[0]);
            mma16816(acc[ng * 2 + 0], ahi, &blo[0]);
            mma16816(acc[ng * 2 + 0], alo, &bh[0]);
            mma16816(acc[ng * 2 + 1], ahi, &bh[2]);
            mma16816(acc[ng * 2 + 1], ahi, &blo[2]);
            mma16816(acc[ng * 2 + 1], alo, &bh[2]);
        }
    }

    // epilogue: relu, dot with cw2, reduce cols across 4-lane group, softmax
    float l0a = 0.f, l1a = 0.f, l0b = 0.f, l1b = 0.f;
    #pragma unroll
    for (int t = 0; t < 16; t++) {
        int col = (t >> 1) * 16 + (t & 1) * 8 + 2 * (lane & 3);
        float bb0 = cb1[col], bb1 = cb1[col + 1];
        float wa0 = cw2[col * 2 + 0],       wb0 = cw2[col * 2 + 1];
        float wa1 = cw2[(col + 1) * 2 + 0], wb1 = cw2[(col + 1) * 2 + 1];
        float h;
        h = fmaxf(acc[t][0] + bb0, 0.f); l0a += h * wa0; l1a += h * wb0;
        h = fmaxf(acc[t][1] + bb1, 0.f); l0a += h * wa1; l1a += h * wb1;
        h = fmaxf(acc[t][2] + bb0, 0.f); l0b += h * wa0; l1b += h * wb0;
        h = fmaxf(acc[t][3] + bb1, 0.f); l0b += h * wa1; l1b += h * wb1;
    }
    #pragma unroll
    for (int m = 1; m < 4; m <<= 1) {
        l0a += __shfl_xor_sync(0xffffffffu, l0a, m);
        l1a += __shfl_xor_sync(0xffffffffu, l1a, m);
        l0b += __shfl_xor_sync(0xffffffffu, l0b, m);
        l1b += __shfl_xor_sync(0xffffffffu, l1b, m);
    }
    if ((lane & 3) == 0) {
        int r0 = blockIdx.x * 128 + wid * 16 + (lane >> 2);
        float mm = fmaxf(l0a, l1a);
        float ea = __expf(l0a - mm), eb = __expf(l1a - mm);
        float inv = 1.f / (ea + eb);
        out[r0 * 2 + 0] = ea * inv;
        out[r0 * 2 + 1] = eb * inv;
        int r1 = r0 + 8;
        mm = fmaxf(l0b, l1b);
        ea = __expf(l0b - mm); eb = __expf(l1b - mm);
        inv = 1.f / (ea + eb);
        out[r1 * 2 + 0] = ea * inv;
        out[r1 * 2 + 1] = eb * inv;
    }
}

// -----------------------------------------------------------------------------
extern "C" void kernel_launch(void* const* d_in, const int* in_sizes, int n_in,
                              void* d_out, int out_size)
{
    const float* feats0 = (const float*)d_in[0];
    const float* feats1 = (const float*)d_in[1];
    const float* t0_pw  = (const float*)d_in[2];
    const float* t0_pb  = (const float*)d_in[3];
    const float* t0_w2  = (const float*)d_in[4];
    const float* t0_b2  = (const float*)d_in[5];
    const float* t0_g   = (const float*)d_in[6];
    const float* t0_be  = (const float*)d_in[7];
    const float* t1_pw  = (const float*)d_in[8];
    const float* t1_pb  = (const float*)d_in[9];
    const float* t1_w2  = (const float*)d_in[10];
    const float* t1_b2  = (const float*)d_in[11];
    const float* t1_g   = (const float*)d_in[12];
    const float* t1_be  = (const float*)d_in[13];
    const float* r_vec  = (const float*)d_in[14];
    const float* attn_u = (const float*)d_in[15];
    const float* attn_i = (const float*)d_in[16];
    const float* su_w1  = (const float*)d_in[17];
    const float* su_b1  = (const float*)d_in[18];
    const float* su_w2  = (const float*)d_in[19];
    const float* si_w1  = (const float*)d_in[20];
    const float* si_b1  = (const float*)d_in[21];
    const float* si_w2  = (const float*)d_in[22];
    const float* cw1    = (const float*)d_in[23];
    const float* cb1    = (const float*)d_in[24];
    const float* cw2    = (const float*)d_in[25];
    const int*   idx0   = (const int*)d_in[26];
    const int*   idx1   = (const int*)d_in[27];
    const int*   emi_u  = (const int*)d_in[28];
    const int*   tgt_u  = (const int*)d_in[29];
    const int*   emi_i  = (const int*)d_in[30];
    const int*   tgt_i  = (const int*)d_in[31];

    static int smem_set = 0;
    if (!smem_set) {
        cudaFuncSetAttribute(k_tower_mma, cudaFuncAttributeMaxDynamicSharedMemorySize, SMTOT);
        cudaFuncSetAttribute(k_sem_mma, cudaFuncAttributeMaxDynamicSharedMemorySize, S_TOT);
        cudaFuncSetAttribute(k_final_mma, cudaFuncAttributeMaxDynamicSharedMemorySize, S_TOT);
        smem_set = 1;
    }

    int NBT = (N0v + 127) / 128 + (N1v + 127) / 128;
    k_tower_mma<<<NBT, 256, SMTOT>>>(feats0, feats1,
        t0_pw, t0_pb, t0_w2, t0_b2, t0_g, t0_be,
        t1_pw, t1_pb, t1_w2, t1_b2, t1_g, t1_be, idx0, idx1, r_vec);
    k_mpf<<<NPv * EPM / 16, 256>>>(emi_u, tgt_u, emi_i, tgt_i, attn_u, attn_i);
    dim3 gsem(BTv / 128, NPv);
    k_sem_mma<<<gsem, 256, S_TOT>>>(su_w1, su_b1, su_w2, si_w1, si_b1, si_w2);
    k_final_mma<<<BTv / 128, 256, S_TOT>>>(cw1, cb1, cw2, (float*)d_out);
}

// round 14
// speedup vs baseline: 1.1460x; 1.0843x over previous
#include <cuda_runtime.h>
#include <cuda_bf16.h>
#include <math.h>
#include <stdint.h>

#define N0v 20000
#define N1v 20000
#define NNODE 40000
#define F0v 512
#define HIDv 64
#define EPM 200000
#define BTv 8192
#define NPv 4

// ---------------- scratch (static device globals; no allocation) -------------
__device__ __align__(16) float g_feat[NNODE * HIDv];     // 10.24 MB
__device__ __align__(16) float g_s[NPv * BTv * 8];       // seg sum of exp(e)
__device__ __align__(16) float g_ret[NPv * BTv * HIDv];  // seg sum of exp(e)*eft
__device__ __align__(16) float g_fr[2 * 3 * 64];         // [side][l][k-pair re/im]
__device__ float g_score[4];

// ================= mma.sync helpers (arch-neutral HMMA path) ================
__device__ __forceinline__ uint32_t smem_u32(const void* p) {
    uint32_t a;
    asm("{ .reg .u64 t; cvta.to.shared.u64 t, %1; cvt.u32.u64 %0, t; }" : "=r"(a) : "l"(p));
    return a;
}
__device__ __forceinline__ void ldsm4(uint32_t addr, uint32_t* r) {
    asm volatile("ldmatrix.sync.aligned.m8n8.x4.shared.b16 {%0,%1,%2,%3}, [%4];"
        : "=r"(r[0]), "=r"(r[1]), "=r"(r[2]), "=r"(r[3]) : "r"(addr));
}
__device__ __forceinline__ void mma16816(float* d, const uint32_t* a, const uint32_t* b) {
    asm volatile(
        "mma.sync.aligned.m16n8k16.row.col.f32.bf16.bf16.f32 "
        "{%0,%1,%2,%3}, {%4,%5,%6,%7}, {%8,%9}, {%0,%1,%2,%3};"
        : "+f"(d[0]), "+f"(d[1]), "+f"(d[2]), "+f"(d[3])
        : "r"(a[0]), "r"(a[1]), "r"(a[2]), "r"(a[3]), "r"(b[0]), "r"(b[1]));
}
__device__ __forceinline__ void split2(float a, float b, uint32_t& hi, uint32_t& lo) {
    __nv_bfloat16 ha = __float2bfloat16(a), hb = __float2bfloat16(b);
    __nv_bfloat16 la = __float2bfloat16(a - __bfloat162float(ha));
    __nv_bfloat16 lb = __float2bfloat16(b - __bfloat162float(hb));
    hi = ((uint32_t)__bfloat16_as_ushort(hb) << 16) | (uint32_t)__bfloat16_as_ushort(ha);
    lo = ((uint32_t)__bfloat16_as_ushort(lb) << 16) | (uint32_t)__bfloat16_as_ushort(la);
}

#define LDA 72          // bf16 elems per smem row (144 B = 9*16, ldmatrix-legal)
#define OF_AHI 0        // A hi: 128 x 72 bf16 = 18432 B
#define OF_ALO 18432    // A lo
#define OF_BHI 36864    // B hi: 64 x 72 bf16 = 9216 B
#define OF_BLO 46080    // B lo
#define SMTOT  55296

// ------- tower via mma.sync bf16 split + fused init: 128 nodes / block -------
__global__ __launch_bounds__(256) void k_tower_mma(
    const float* __restrict__ feats0, const float* __restrict__ feats1,
    const float* __restrict__ pw0, const float* __restrict__ pb0,
    const float* __restrict__ w20, const float* __restrict__ b20,
    const float* __restrict__ gg0, const float* __restrict__ be0,
    const float* __restrict__ pw1, const float* __restrict__ pb1,
    const float* __restrict__ w21, const float* __restrict__ b21,
    const float* __restrict__ gg1, const float* __restrict__ be1,
    const int* __restrict__ idx0, const int* __restrict__ idx1,
    const float* __restrict__ r_vec)
{
    extern __shared__ __align__(16) char sm[];
    uint32_t sbase = smem_u32(sm);
    int tid = threadIdx.x;
    int lane = tid & 31;
    int wid = tid >> 5;

    // ---- fused init: zero accumulators (grid-strided), g_fr on block 0 ------
    {
        int gt = blockIdx.x * 256 + tid;
        int gstride = gridDim.x * 256;
        float4 z4 = make_float4(0.f, 0.f, 0.f, 0.f);
        for (int i = gt; i < NPv * BTv * HIDv / 4; i += gstride)
            ((float4*)g_ret)[i] = z4;
        for (int i = gt; i < NPv * BTv * 8 / 4; i += gstride)
            ((float4*)g_s)[i] = z4;
        if (blockIdx.x == 0) {
            if (tid < 4) g_score[tid] = 0.f;
            if (tid < 32) {
                int k = tid;
                float rr = r_vec[k * 2 + 0], ri = r_vec[k * 2 + 1];
                float nm = sqrtf(rr * rr + ri * ri);
                float cr = rr / nm, ci = ri / nm;
                float u1r = cr,  u1i = -ci;
                float u0r = u1r * cr - u1i * ci;
                float u0i = u1r * ci + u1i * cr;
                g_fr[(0 * 3 + 0) * 64 + 2 * k] = u0r; g_fr[(0 * 3 + 0) * 64 + 2 * k + 1] = u0i;
                g_fr[(0 * 3 + 1) * 64 + 2 * k] = u1r; g_fr[(0 * 3 + 1) * 64 + 2 * k + 1] = u1i;
                g_fr[(0 * 3 + 2) * 64 + 2 * k] = 1.f; g_fr[(0 * 3 + 2) * 64 + 2 * k + 1] = 0.f;
                float i1r = cr,  i1i = ci;
                float i0r = i1r * cr - i1i * (-ci);
                float i0i = i1r * (-ci) + i1i * cr;
                g_fr[(1 * 3 + 0) * 64 + 2 * k] = i0r; g_fr[(1 * 3 + 0) * 64 + 2 * k + 1] = i0i;
                g_fr[(1 * 3 + 1) * 64 + 2 * k] = i1r; g_fr[(1 * 3 + 1) * 64 + 2 * k + 1] = i1i;
                g_fr[(1 * 3 + 2) * 64 + 2 * k] = 1.f; g_fr[(1 * 3 + 2) * 64 + 2 * k + 1] = 0.f;
            }
        }
    }

    const int NB0 = (N0v + 127) / 128;
    int bt = blockIdx.x;
    int tower = (bt >= NB0) ? 1 : 0;
    int bl = tower ? bt - NB0 : bt;
    int nbase = bl * 128;
    int Nlim = tower ? N1v : N0v;
    int valid = Nlim - nbase; if (valid > 128) valid = 128;
    const float* X  = tower ? feats1 : feats0;
    const float* PW = tower ? pw1 : pw0;
    const float* PB = tower ? pb1 : pb0;
    const float* W2 = tower ? w21 : w20;
    const float* B2 = tower ? b21 : b20;
    const float* GG = tower ? gg1 : gg0;
    const float* BE = tower ? be1 : be0;
    const int*  IDX = tower ? idx1 : idx0;

    int ra    = lane & 15;
    int kadd  = (lane >> 4) * 8;
    int nB    = ((lane >> 4) << 3) + (lane & 7);
    int kB    = ((lane >> 3) & 1) * 8;

    float acc[8][4];
    #pragma unroll
    for (int nt = 0; nt < 8; nt++)
        #pragma unroll
        for (int i = 0; i < 4; i++) acc[nt][i] = 0.f;

    // =================== GEMM1: X[128x512] @ W1[512x64] ======================
    for (int c = 0; c < 8; c++) {
        #pragma unroll
        for (int it = 0; it < 8; it++) {
            int idx = tid + it * 256;
            int row = idx >> 4, q = idx & 15;
            int gr = nbase + row; if (gr >= Nlim) gr = Nlim - 1;
            float4 v = *(const float4*)&X[(size_t)gr * F0v + c * 64 + q * 4];
            uint2 H, L;
            split2(v.x, v.y, H.x, L.x);
            split2(v.z, v.w, H.y, L.y);
            uint32_t off = (uint32_t)(row * LDA + q * 4) * 2;
            *(uint2*)(sm + OF_AHI + off) = H;
            *(uint2*)(sm + OF_ALO + off) = L;
        }
        #pragma unroll
        for (int it = 0; it < 4; it++) {
            int idx = tid + it * 256;
            int k = idx >> 4, q = (idx & 15) * 4;
            float4 w = *(const float4*)&PW[(size_t)(c * 64 + k) * HIDv + q];
            float wv[4] = {w.x, w.y, w.z, w.w};
            #pragma unroll
            for (int j = 0; j < 4; j++) {
                int n = q + j;
                int kp = k ^ (((n >> 3) & 7) << 3);
                __nv_bfloat16 h = __float2bfloat16(wv[j]);
                __nv_bfloat16 l = __float2bfloat16(wv[j] - __bfloat162float(h));
                uint32_t off = (uint32_t)(n * LDA + kp) * 2;
                *(__nv_bfloat16*)(sm + OF_BHI + off) = h;
                *(__nv_bfloat16*)(sm + OF_BLO + off) = l;
            }
        }
        __syncthreads();
        #pragma unroll
        for (int ks = 0; ks < 4; ks++) {
            uint32_t ahi[4], alo[4], bh[16], blo[16];
            uint32_t aoff = (uint32_t)((wid * 16 + ra) * LDA + ks * 16 + kadd) * 2;
            ldsm4(sbase + OF_AHI + aoff, ahi);
            ldsm4(sbase + OF_ALO + aoff, alo);
            #pragma unroll
            for (int ng = 0; ng < 4; ng++) {
                int n = ng * 16 + nB;
                int kp = (ks * 16 + kB) ^ (((n >> 3) & 7) << 3);
                uint32_t boff = (uint32_t)(n * LDA + kp) * 2;
                ldsm4(sbase + OF_BHI + boff, &bh[ng * 4]);
                ldsm4(sbase + OF_BLO + boff, &blo[ng * 4]);
            }
            #pragma unroll
            for (int nt = 0; nt < 8; nt++) {
                mma16816(acc[nt], ahi, &bh[nt * 2]);
                mma16816(acc[nt], ahi, &blo[nt * 2]);
                mma16816(acc[nt], alo, &bh[nt * 2]);
            }
        }
        __syncthreads();
    }

    // =================== z = acc + b1; h = gelu(z) -> A smem =================
    int nlo = 2 * (lane & 3);
    int r0 = wid * 16 + (lane >> 2);
    int r1 = r0 + 8;
    float z[8][4];
    #pragma unroll
    for (int nt = 0; nt < 8; nt++) {
        float b0 = PB[nt * 8 + nlo], b1v = PB[nt * 8 + nlo + 1];
        z[nt][0] = acc[nt][0] + b0;  z[nt][1] = acc[nt][1] + b1v;
        z[nt][2] = acc[nt][2] + b0;  z[nt][3] = acc[nt][3] + b1v;
        float h0 = 0.5f * z[nt][0] * (1.f + erff(z[nt][0] * 0.70710678118654752f));
        float h1 = 0.5f * z[nt][1] * (1.f + erff(z[nt][1] * 0.70710678118654752f));
        float h2 = 0.5f * z[nt][2] * (1.f + erff(z[nt][2] * 0.70710678118654752f));
        float h3 = 0.5f * z[nt][3] * (1.f + erff(z[nt][3] * 0.70710678118654752f));
        uint32_t H01, L01, H23, L23;
        split2(h0, h1, H01, L01);
        split2(h2, h3, H23, L23);
        uint32_t o0 = (uint32_t)(r0 * LDA + nt * 8 + nlo) * 2;
        uint32_t o1 = (uint32_t)(r1 * LDA + nt * 8 + nlo) * 2;
        *(uint32_t*)(sm + OF_AHI + o0) = H01;
        *(uint32_t*)(sm + OF_ALO + o0) = L01;
        *(uint32_t*)(sm + OF_AHI + o1) = H23;
        *(uint32_t*)(sm + OF_ALO + o1) = L23;
        acc[nt][0] = 0.f; acc[nt][1] = 0.f; acc[nt][2] = 0.f; acc[nt][3] = 0.f;
    }
    #pragma unroll
    for (int it = 0; it < 4; it++) {
        int idx = tid + it * 256;
        int k = idx >> 4, q = (idx & 15) * 4;
        float4 w = *(const float4*)&W2[(size_t)k * HIDv + q];
        float wv[4] = {w.x, w.y, w.z, w.w};
        #pragma unroll
        for (int j = 0; j < 4; j++) {
            int n = q + j;
            int kp = k ^ (((n >> 3) & 7) << 3);
            __nv_bfloat16 h = __float2bfloat16(wv[j]);
            __nv_bfloat16 l = __float2bfloat16(wv[j] - __bfloat162float(h));
            uint32_t off = (uint32_t)(n * LDA + kp) * 2;
            *(__nv_bfloat16*)(sm + OF_BHI + off) = h;
            *(__nv_bfloat16*)(sm + OF_BLO + off) = l;
        }
    }
    __syncthreads();

    // =================== GEMM2: h[128x64] @ W2[64x64] ========================
    #pragma unroll
    for (int ks = 0; ks < 4; ks++) {
        uint32_t ahi[4], alo[4], bh[16], blo[16];
        uint32_t aoff = (uint32_t)((wid * 16 + ra) * LDA + ks * 16 + kadd) * 2;
        ldsm4(sbase + OF_AHI + aoff, ahi);
        ldsm4(sbase + OF_ALO + aoff, alo);
        #pragma unroll
        for (int ng = 0; ng < 4; ng++) {
            int n = ng * 16 + nB;
            int kp = (ks * 16 + kB) ^ (((n >> 3) & 7) << 3);
            uint32_t boff = (uint32_t)(n * LDA + kp) * 2;
            ldsm4(sbase + OF_BHI + boff, &bh[ng * 4]);
            ldsm4(sbase + OF_BLO + boff, &blo[ng * 4]);
        }
        #pragma unroll
        for (int nt = 0; nt < 8; nt++) {
            mma16816(acc[nt], ahi, &bh[nt * 2]);
            mma16816(acc[nt], ahi, &blo[nt * 2]);
            mma16816(acc[nt], alo, &bh[nt * 2]);
        }
    }

    // =================== y = acc + b2 + z; LayerNorm; store ==================
    float y[8][4];
    float s1a = 0.f, s2a = 0.f, s1b = 0.f, s2b = 0.f;
    #pragma unroll
    for (int nt = 0; nt < 8; nt++) {
        float b0 = B2[nt * 8 + nlo], b1v = B2[nt * 8 + nlo + 1];
        y[nt][0] = acc[nt][0] + b0 + z[nt][0];
        y[nt][1] = acc[nt][1] + b1v + z[nt][1];
        y[nt][2] = acc[nt][2] + b0 + z[nt][2];
        y[nt][3] = acc[nt][3] + b1v + z[nt][3];
        s1a += y[nt][0] + y[nt][1];
        s2a += y[nt][0] * y[nt][0] + y[nt][1] * y[nt][1];
        s1b += y[nt][2] + y[nt][3];
        s2b += y[nt][2] * y[nt][2] + y[nt][3] * y[nt][3];
    }
    #pragma unroll
    for (int m = 1; m < 4; m <<= 1) {
        s1a += __shfl_xor_sync(0xffffffffu, s1a, m);
        s2a += __shfl_xor_sync(0xffffffffu, s2a, m);
        s1b += __shfl_xor_sync(0xffffffffu, s1b, m);
        s2b += __shfl_xor_sync(0xffffffffu, s2b, m);
    }
    float mu0 = s1a * (1.f / 64.f);
    float rs0 = rsqrtf(s2a * (1.f / 64.f) - mu0 * mu0 + 1e-5f);
    float mu1 = s1b * (1.f / 64.f);
    float rs1 = rsqrtf(s2b * (1.f / 64.f) - mu1 * mu1 + 1e-5f);
    if (r0 < valid) {
        int gn = IDX[nbase + r0];
        #pragma unroll
        for (int nt = 0; nt < 8; nt++) {
            float2 o;
            o.x = (y[nt][0] - mu0) * rs0 * GG[nt * 8 + nlo] + BE[nt * 8 + nlo];
            o.y = (y[nt][1] - mu0) * rs0 * GG[nt * 8 + nlo + 1] + BE[nt * 8 + nlo + 1];
            *(float2*)&g_feat[(size_t)gn * HIDv + nt * 8 + nlo] = o;
        }
    }
    if (r1 < valid) {
        int gn = IDX[nbase + r1];
        #pragma unroll
        for (int nt = 0; nt < 8; nt++) {
            float2 o;
            o.x = (y[nt][2] - mu1) * rs1 * GG[nt * 8 + nlo] + BE[nt * 8 + nlo];
            o.y = (y[nt][3] - mu1) * rs1 * GG[nt * 8 + nlo + 1] + BE[nt * 8 + nlo + 1];
            *(float2*)&g_feat[(size_t)gn * HIDv + nt * 8 + nlo] = o;
        }
    }
}

// ---- fused metapath: gather+rotate+mean -> e -> exp -> seg sums (no max) ----
__global__ __launch_bounds__(256) void k_mpf(
    const int* __restrict__ emi_u, const int* __restrict__ tgt_u,
    const int* __restrict__ emi_i, const int* __restrict__ tgt_i,
    const float* __restrict__ attn_u, const float* __restrict__ attn_i)
{
    int warp = blockIdx.x * (blockDim.x >> 5) + (threadIdx.x >> 5);
    int lane = threadIdx.x & 31;
    int half = lane >> 4;
    int sl = lane & 15;
    int inst = warp * 2 + half;
    int p = inst / EPM;
    int i = inst - p * EPM;
    int side = p >> 1, pl = p & 1;
    const int* emi = side ? emi_i : emi_u;
    const int* tgt = side ? tgt_i : tgt_u;
    const float* attn = side ? attn_i : attn_u;

    int n = 0;
    if (sl < 3) n = emi[((size_t)pl * EPM + i) * 3 + sl];
    float re0 = 0.f, im0 = 0.f, re1 = 0.f, im1 = 0.f;
    #pragma unroll
    for (int l = 0; l < 3; l++) {
        int nl = __shfl_sync(0xffffffffu, n, half * 16 + l);
        float4 v  = *(const float4*)&g_feat[(size_t)nl * HIDv + sl * 4];
        float4 fr = *(const float4*)&g_fr[(side * 3 + l) * 64 + sl * 4];
        re0 += v.x * fr.x - v.y * fr.y;
        im0 += v.x * fr.y + v.y * fr.x;
        re1 += v.z * fr.z - v.w * fr.w;
        im1 += v.z * fr.w + v.w * fr.z;
    }
    re0 *= (1.f / 3.f); im0 *= (1.f / 3.f);
    re1 *= (1.f / 3.f); im1 *= (1.f / 3.f);

    int h = sl >> 1;
    int dpart = (sl & 1) * 4;
    float4 av = *(const float4*)&attn[(pl * 8 + h) * 8 + dpart];
    float ep = re0 * av.x + im0 * av.y + re1 * av.z + im1 * av.w;
    ep += __shfl_xor_sync(0xffffffffu, ep, 1);
    float ev = ep > 0.f ? ep : 0.01f * ep;
    float a = __expf(ev);

    int t = tgt[(size_t)pl * EPM + i];
    size_t seg = (size_t)p * BTv + t;
    if ((sl & 1) == 0) atomicAdd(&g_s[seg * 8 + h], a);
    atomicAdd((float4*)&g_ret[seg * HIDv + sl * 4],
              make_float4(a * re0, a * im0, a * re1, a * im1));
}

// -------- semantic via mma.sync: 128 rows x 128 cols per block ---------------
#define S_LDA 72
#define S_AHI 0
#define S_ALO 18432
#define S_BHI 36864
#define S_BLO 55296
#define S_TOT 73728

__global__ __launch_bounds__(256) void k_sem_mma(
    const float* __restrict__ su_w1, const float* __restrict__ su_b1, const float* __restrict__ su_w2,
    const float* __restrict__ si_w1, const float* __restrict__ si_b1, const float* __restrict__ si_w2)
{
    extern __shared__ __align__(16) char sm2[];
    uint32_t sbase = smem_u32(sm2);
    __shared__ float red[8];
    int p = blockIdx.y;
    const float* w1 = (p < 2) ? su_w1 : si_w1;
    const float* b1 = (p < 2) ? su_b1 : si_b1;
    const float* w2 = (p < 2) ? su_w2 : si_w2;
    int tid = threadIdx.x;
    int lane = tid & 31;
    int wid = tid >> 5;

    #pragma unroll
    for (int it = 0; it < 8; it++) {
        int idx = tid + it * 256;
        int k = idx >> 5;
        int q = (idx & 31) * 4;
        float4 w = *(const float4*)&w1[(size_t)k * 128 + q];
        float wv[4] = {w.x, w.y, w.z, w.w};
        #pragma unroll
        for (int j = 0; j < 4; j++) {
            int n = q + j;
            int kp = k ^ (((n >> 3) & 7) << 3);
            __nv_bfloat16 h = __float2bfloat16(wv[j]);
            __nv_bfloat16 l = __float2bfloat16(wv[j] - __bfloat162float(h));
            uint32_t off = (uint32_t)(n * S_LDA + kp) * 2;
            *(__nv_bfloat16*)(sm2 + S_BHI + off) = h;
            *(__nv_bfloat16*)(sm2 + S_BLO + off) = l;
        }
    }
    {
        int row = tid >> 1;
        int b_g = blockIdx.x * 128 + row;
        size_t seg = (size_t)p * BTv + b_g;
        int cbase = (tid & 1) * 32;
        #pragma unroll
        for (int cc = 0; cc < 8; cc++) {
            int c0 = cbase + cc * 4;
            float sd = g_s[seg * 8 + (c0 >> 3)] + 1e-9f;
            float inv = 1.f / sd;
            float4 v = *(const float4*)&g_ret[seg * HIDv + c0];
            v.x *= inv; v.y *= inv; v.z *= inv; v.w *= inv;
            v.x = v.x > 0.f ? v.x : expf(v.x) - 1.f;
            v.y = v.y > 0.f ? v.y : expf(v.y) - 1.f;
            v.z = v.z > 0.f ? v.z : expf(v.z) - 1.f;
            v.w = v.w > 0.f ? v.w : expf(v.w) - 1.f;
            *(float4*)&g_ret[seg * HIDv + c0] = v;    // persist for k_final
            uint2 H, L;
            split2(v.x, v.y, H.x, L.x);
            split2(v.z, v.w, H.y, L.y);
            uint32_t off = (uint32_t)(row * S_LDA + c0) * 2;
            *(uint2*)(sm2 + S_AHI + off) = H;
            *(uint2*)(sm2 + S_ALO + off) = L;
        }
    }
    __syncthreads();

    int ra   = lane & 15;
    int kadd = (lane >> 4) * 8;
    int nB   = ((lane >> 4) << 3) + (lane & 7);
    int kB   = ((lane >> 3) & 1) * 8;

    float acc[16][4];
    #pragma unroll
    for (int t = 0; t < 16; t++)
        #pragma unroll
        for (int i = 0; i < 4; i++) acc[t][i] = 0.f;

    #pragma unroll
    for (int ks = 0; ks < 4; ks++) {
        uint32_t ahi[4], alo[4];
        uint32_t aoff = (uint32_t)((wid * 16 + ra) * S_LDA + ks * 16 + kadd) * 2;
        ldsm4(sbase + S_AHI + aoff, ahi);
        ldsm4(sbase + S_ALO + aoff, alo);
        #pragma unroll
        for (int ng = 0; ng < 8; ng++) {
            int n = ng * 16 + nB;
            int kp = (ks * 16 + kB) ^ (((n >> 3) & 7) << 3);
            uint32_t boff = (uint32_t)(n * S_LDA + kp) * 2;
            uint32_t bh[4], blo[4];
            ldsm4(sbase + S_BHI + boff, bh);
            ldsm4(sbase + S_BLO + boff, blo);
            mma16816(acc[ng * 2 + 0], ahi, &bh[0]);
            mma16816(acc[ng * 2 + 0], ahi, &blo[0]);
            mma16816(acc[ng * 2 + 0], alo, &bh[0]);
            mma16816(acc[ng * 2 + 1], ahi, &bh[2]);
            mma16816(acc[ng * 2 + 1], ahi, &blo[2]);
            mma16816(acc[ng * 2 + 1], alo, &bh[2]);
        }
    }

    float lsum = 0.f;
    #pragma unroll
    for (int t = 0; t < 16; t++) {
        int col = (t >> 1) * 16 + (t & 1) * 8 + 2 * (lane & 3);
        float bb0 = b1[col], bb1 = b1[col + 1];
        float ww0 = w2[col], ww1 = w2[col + 1];
        lsum += tanhf(acc[t][0] + bb0) * ww0 + tanhf(acc[t][1] + bb1) * ww1
              + tanhf(acc[t][2] + bb0) * ww0 + tanhf(acc[t][3] + bb1) * ww1;
    }
    #pragma unroll
    for (int m = 16; m; m >>= 1) lsum += __shfl_xor_sync(0xffffffffu, lsum, m);
    if (lane == 0) red[wid] = lsum;
    __syncthreads();
    if (tid == 0) {
        float s = 0.f;
        #pragma unroll
        for (int w = 0; w < 8; w++) s += red[w];
        atomicAdd(&g_score[p], s);
    }
}

// -------- final via mma.sync: 128 rows x 128 cols per block ------------------
__global__ __launch_bounds__(256) void k_final_mma(
    const float* __restrict__ cw1, const float* __restrict__ cb1,
    const float* __restrict__ cw2, float* __restrict__ out)
{
    extern __shared__ __align__(16) char sm3[];
    uint32_t sbase = smem_u32(sm3);
    int tid = threadIdx.x;
    int lane = tid & 31;
    int wid = tid >> 5;

    float s0 = g_score[0] * (1.f / BTv), s1 = g_score[1] * (1.f / BTv);
    float s2 = g_score[2] * (1.f / BTv), s3 = g_score[3] * (1.f / BTv);
    float mu = fmaxf(s0, s1);
    float e0 = __expf(s0 - mu), e1 = __expf(s1 - mu);
    float bu0 = e0 / (e0 + e1), bu1 = e1 / (e0 + e1);
    float mi = fmaxf(s2, s3);
    float e2 = __expf(s2 - mi), e3 = __expf(s3 - mi);
    float bi0 = e2 / (e2 + e3), bi1 = e3 / (e2 + e3);

    // cw1[64k x 128n] -> B smem [n][k^swz] bf16 hi/lo
    #pragma unroll
    for (int it = 0; it < 8; it++) {
        int idx = tid + it * 256;
        int k = idx >> 5;
        int q = (idx & 31) * 4;
        float4 w = *(const float4*)&cw1[(size_t)k * 128 + q];
        float wv[4] = {w.x, w.y, w.z, w.w};
        #pragma unroll
        for (int j = 0; j < 4; j++) {
            int n = q + j;
            int kp = k ^ (((n >> 3) & 7) << 3);
            __nv_bfloat16 h = __float2bfloat16(wv[j]);
            __nv_bfloat16 l = __float2bfloat16(wv[j] - __bfloat162float(h));
            uint32_t off = (uint32_t)(n * S_LDA + kp) * 2;
            *(__nv_bfloat16*)(sm3 + S_BHI + off) = h;
            *(__nv_bfloat16*)(sm3 + S_BLO + off) = l;
        }
    }
    // rows: beta-combine + product -> A smem bf16 hi/lo
    {
        int row = tid >> 1;
        int b_g = blockIdx.x * 128 + row;
        size_t o = (size_t)b_g * HIDv;
        int cbase = (tid & 1) * 32;
        #pragma unroll
        for (int cc = 0; cc < 8; cc++) {
            int c0 = cbase + cc * 4;
            float4 r0 = *(const float4*)&g_ret[o + c0];
            float4 r1 = *(const float4*)&g_ret[(size_t)BTv * HIDv + o + c0];
            float4 r2 = *(const float4*)&g_ret[(size_t)2 * BTv * HIDv + o + c0];
            float4 r3 = *(const float4*)&g_ret[(size_t)3 * BTv * HIDv + o + c0];
            float4 v;
            v.x = (bu0 * r0.x + bu1 * r1.x) * (bi0 * r2.x + bi1 * r3.x);
            v.y = (bu0 * r0.y + bu1 * r1.y) * (bi0 * r2.y + bi1 * r3.y);
            v.z = (bu0 * r0.z + bu1 * r1.z) * (bi0 * r2.z + bi1 * r3.z);
            v.w = (bu0 * r0.w + bu1 * r1.w) * (bi0 * r2.w + bi1 * r3.w);
            uint2 H, L;
            split2(v.x, v.y, H.x, L.x);
            split2(v.z, v.w, H.y, L.y);
            uint32_t off = (uint32_t)(row * S_LDA + c0) * 2;
            *(uint2*)(sm3 + S_AHI + off) = H;
            *(uint2*)(sm3 + S_ALO + off) = L;
        }
    }
    __syncthreads();

    int ra   = lane & 15;
    int kadd = (lane >> 4) * 8;
    int nB   = ((lane >> 4) << 3) + (lane & 7);
    int kB   = ((lane >> 3) & 1) * 8;

    float acc[16][4];
    #pragma unroll
    for (int t = 0; t < 16; t++)
        #pragma unroll
        for (int i = 0; i < 4; i++) acc[t][i] = 0.f;

    #pragma unroll
    for (int ks = 0; ks < 4; ks++) {
        uint32_t ahi[4], alo[4];
        uint32_t aoff = (uint32_t)((wid * 16 + ra) * S_LDA + ks * 16 + kadd) * 2;
        ldsm4(sbase + S_AHI + aoff, ahi);
        ldsm4(sbase + S_ALO + aoff, alo);
        #pragma unroll
        for (int ng = 0; ng < 8; ng++) {
            int n = ng * 16 + nB;
            int kp = (ks * 16 + kB) ^ (((n >> 3) & 7) << 3);
            uint32_t boff = (uint32_t)(n * S_LDA + kp) * 2;
            uint32_t bh[4], blo[4];
            ldsm4(sbase + S_BHI + boff, bh);
            ldsm4(sbase + S_BLO + boff, blo);
            mma16816(acc[ng * 2 + 0], ahi, &bh[0]);
            mma16816(acc[ng * 2 + 0], ahi, &blo[0]);
            mma16816(acc[ng * 2 + 0], alo, &bh[0]);
            mma16816(acc[ng * 2 + 1], ahi, &bh[2]);
            mma16816(acc[ng * 2 + 1], ahi, &blo[2]);
            mma16816(acc[ng * 2 + 1], alo, &bh[2]);
        }
    }

    // epilogue: relu, dot with cw2, reduce cols across 4-lane group, softmax
    float l0a = 0.f, l1a = 0.f, l0b = 0.f, l1b = 0.f;
    #pragma unroll
    for (int t = 0; t < 16; t++) {
        int col = (t >> 1) * 16 + (t & 1) * 8 + 2 * (lane & 3);
        float bb0 = cb1[col], bb1 = cb1[col + 1];
        float wa0 = cw2[col * 2 + 0],       wb0 = cw2[col * 2 + 1];
        float wa1 = cw2[(col + 1) * 2 + 0], wb1 = cw2[(col + 1) * 2 + 1];
        float h;
        h = fmaxf(acc[t][0] + bb0, 0.f); l0a += h * wa0; l1a += h * wb0;
        h = fmaxf(acc[t][1] + bb1, 0.f); l0a += h * wa1; l1a += h * wb1;
        h = fmaxf(acc[t][2] + bb0, 0.f); l0b += h * wa0; l1b += h * wb0;
        h = fmaxf(acc[t][3] + bb1, 0.f); l0b += h * wa1; l1b += h * wb1;
    }
    #pragma unroll
    for (int m = 1; m < 4; m <<= 1) {
        l0a += __shfl_xor_sync(0xffffffffu, l0a, m);
        l1a += __shfl_xor_sync(0xffffffffu, l1a, m);
        l0b += __shfl_xor_sync(0xffffffffu, l0b, m);
        l1b += __shfl_xor_sync(0xffffffffu, l1b, m);
    }
    if ((lane & 3) == 0) {
        int r0 = blockIdx.x * 128 + wid * 16 + (lane >> 2);
        float mm = fmaxf(l0a, l1a);
        float ea = __expf(l0a - mm), eb = __expf(l1a - mm);
        float inv = 1.f / (ea + eb);
        out[r0 * 2 + 0] = ea * inv;
        out[r0 * 2 + 1] = eb * inv;
        int r1 = r0 + 8;
        mm = fmaxf(l0b, l1b);
        ea = __expf(l0b - mm); eb = __expf(l1b - mm);
        inv = 1.f / (ea + eb);
        out[r1 * 2 + 0] = ea * inv;
        out[r1 * 2 + 1] = eb * inv;
    }
}

// -----------------------------------------------------------------------------
extern "C" void kernel_launch(void* const* d_in, const int* in_sizes, int n_in,
                              void* d_out, int out_size)
{
    const float* feats0 = (const float*)d_in[0];
    const float* feats1 = (const float*)d_in[1];
    const float* t0_pw  = (const float*)d_in[2];
    const float* t0_pb  = (const float*)d_in[3];
    const float* t0_w2  = (const float*)d_in[4];
    const float* t0_b2  = (const float*)d_in[5];
    const float* t0_g   = (const float*)d_in[6];
    const float* t0_be  = (const float*)d_in[7];
    const float* t1_pw  = (const float*)d_in[8];
    const float* t1_pb  = (const float*)d_in[9];
    const float* t1_w2  = (const float*)d_in[10];
    const float* t1_b2  = (const float*)d_in[11];
    const float* t1_g   = (const float*)d_in[12];
    const float* t1_be  = (const float*)d_in[13];
    const float* r_vec  = (const float*)d_in[14];
    const float* attn_u = (const float*)d_in[15];
    const float* attn_i = (const float*)d_in[16];
    const float* su_w1  = (const float*)d_in[17];
    const float* su_b1  = (const float*)d_in[18];
    const float* su_w2  = (const float*)d_in[19];
    const float* si_w1  = (const float*)d_in[20];
    const float* si_b1  = (const float*)d_in[21];
    const float* si_w2  = (const float*)d_in[22];
    const float* cw1    = (const float*)d_in[23];
    const float* cb1    = (const float*)d_in[24];
    const float* cw2    = (const float*)d_in[25];
    const int*   idx0   = (const int*)d_in[26];
    const int*   idx1   = (const int*)d_in[27];
    const int*   emi_u  = (const int*)d_in[28];
    const int*   tgt_u  = (const int*)d_in[29];
    const int*   emi_i  = (const int*)d_in[30];
    const int*   tgt_i  = (const int*)d_in[31];

    static int smem_set = 0;
    if (!smem_set) {
        cudaFuncSetAttribute(k_tower_mma, cudaFuncAttributeMaxDynamicSharedMemorySize, SMTOT);
        cudaFuncSetAttribute(k_sem_mma, cudaFuncAttributeMaxDynamicSharedMemorySize, S_TOT);
        cudaFuncSetAttribute(k_final_mma, cudaFuncAttributeMaxDynamicSharedMemorySize, S_TOT);
        smem_set = 1;
    }

    int NBT = (N0v + 127) / 128 + (N1v + 127) / 128;
    k_tower_mma<<<NBT, 256, SMTOT>>>(feats0, feats1,
        t0_pw, t0_pb, t0_w2, t0_b2, t0_g, t0_be,
        t1_pw, t1_pb, t1_w2, t1_b2, t1_g, t1_be, idx0, idx1, r_vec);
    k_mpf<<<NPv * EPM / 16, 256>>>(emi_u, tgt_u, emi_i, tgt_i, attn_u, attn_i);
    dim3 gsem(BTv / 128, NPv);
    k_sem_mma<<<gsem, 256, S_TOT>>>(su_w1, su_b1, su_w2, si_w1, si_b1, si_w2);
    k_final_mma<<<BTv / 128, 256, S_TOT>>>(cw1, cb1, cw2, (float*)d_out);
}

// round 15
// speedup vs baseline: 1.1506x; 1.0040x over previous
#include <cuda_runtime.h>
#include <cuda_bf16.h>
#include <math.h>
#include <stdint.h>

#define N0v 20000
#define N1v 20000
#define NNODE 40000
#define F0v 512
#define HIDv 64
#define EPM 200000
#define BTv 8192
#define NPv 4

// ---------------- scratch (static device globals; no allocation) -------------
__device__ __align__(16) float g_feat[NNODE * HIDv];     // 10.24 MB
__device__ __align__(16) float g_s[NPv * BTv * 8];       // seg sum of exp(e)
__device__ __align__(16) float g_ret[NPv * BTv * HIDv];  // seg sum of exp(e)*eft
__device__ __align__(16) float g_fr[2 * 3 * 64];         // [side][l][k-pair re/im]
__device__ float g_score[4];

// ================= mma.sync helpers (arch-neutral HMMA path) ================
__device__ __forceinline__ uint32_t smem_u32(const void* p) {
    uint32_t a;
    asm("{ .reg .u64 t; cvta.to.shared.u64 t, %1; cvt.u32.u64 %0, t; }" : "=r"(a) : "l"(p));
    return a;
}
__device__ __forceinline__ void ldsm4(uint32_t addr, uint32_t* r) {
    asm volatile("ldmatrix.sync.aligned.m8n8.x4.shared.b16 {%0,%1,%2,%3}, [%4];"
        : "=r"(r[0]), "=r"(r[1]), "=r"(r[2]), "=r"(r[3]) : "r"(addr));
}
__device__ __forceinline__ void mma16816(float* d, const uint32_t* a, const uint32_t* b) {
    asm volatile(
        "mma.sync.aligned.m16n8k16.row.col.f32.bf16.bf16.f32 "
        "{%0,%1,%2,%3}, {%4,%5,%6,%7}, {%8,%9}, {%0,%1,%2,%3};"
        : "+f"(d[0]), "+f"(d[1]), "+f"(d[2]), "+f"(d[3])
        : "r"(a[0]), "r"(a[1]), "r"(a[2]), "r"(a[3]), "r"(b[0]), "r"(b[1]));
}
__device__ __forceinline__ void split2(float a, float b, uint32_t& hi, uint32_t& lo) {
    __nv_bfloat16 ha = __float2bfloat16(a), hb = __float2bfloat16(b);
    __nv_bfloat16 la = __float2bfloat16(a - __bfloat162float(ha));
    __nv_bfloat16 lb = __float2bfloat16(b - __bfloat162float(hb));
    hi = ((uint32_t)__bfloat16_as_ushort(hb) << 16) | (uint32_t)__bfloat16_as_ushort(ha);
    lo = ((uint32_t)__bfloat16_as_ushort(lb) << 16) | (uint32_t)__bfloat16_as_ushort(la);
}

#define LDA 72          // bf16 elems per smem row (144 B = 9*16, ldmatrix-legal)
#define OF_AHI 0        // A hi: 128 x 72 bf16 = 18432 B
#define OF_ALO 18432    // A lo
#define OF_BHI 36864    // B hi: 64 x 72 bf16 = 9216 B
#define OF_BLO 46080    // B lo
#define SMTOT  55296

// ------- tower via mma.sync bf16 split + fused init: 128 nodes / block -------
__global__ __launch_bounds__(256) void k_tower_mma(
    const float* __restrict__ feats0, const float* __restrict__ feats1,
    const float* __restrict__ pw0, const float* __restrict__ pb0,
    const float* __restrict__ w20, const float* __restrict__ b20,
    const float* __restrict__ gg0, const float* __restrict__ be0,
    const float* __restrict__ pw1, const float* __restrict__ pb1,
    const float* __restrict__ w21, const float* __restrict__ b21,
    const float* __restrict__ gg1, const float* __restrict__ be1,
    const int* __restrict__ idx0, const int* __restrict__ idx1,
    const float* __restrict__ r_vec)
{
    extern __shared__ __align__(16) char sm[];
    uint32_t sbase = smem_u32(sm);
    int tid = threadIdx.x;
    int lane = tid & 31;
    int wid = tid >> 5;

    // ---- fused init: zero accumulators (grid-strided), g_fr on block 0 ------
    {
        int gt = blockIdx.x * 256 + tid;
        int gstride = gridDim.x * 256;
        float4 z4 = make_float4(0.f, 0.f, 0.f, 0.f);
        for (int i = gt; i < NPv * BTv * HIDv / 4; i += gstride)
            ((float4*)g_ret)[i] = z4;
        for (int i = gt; i < NPv * BTv * 8 / 4; i += gstride)
            ((float4*)g_s)[i] = z4;
        if (blockIdx.x == 0) {
            if (tid < 4) g_score[tid] = 0.f;
            if (tid < 32) {
                int k = tid;
                float rr = r_vec[k * 2 + 0], ri = r_vec[k * 2 + 1];
                float nm = sqrtf(rr * rr + ri * ri);
                float cr = rr / nm, ci = ri / nm;
                float u1r = cr,  u1i = -ci;
                float u0r = u1r * cr - u1i * ci;
                float u0i = u1r * ci + u1i * cr;
                g_fr[(0 * 3 + 0) * 64 + 2 * k] = u0r; g_fr[(0 * 3 + 0) * 64 + 2 * k + 1] = u0i;
                g_fr[(0 * 3 + 1) * 64 + 2 * k] = u1r; g_fr[(0 * 3 + 1) * 64 + 2 * k + 1] = u1i;
                g_fr[(0 * 3 + 2) * 64 + 2 * k] = 1.f; g_fr[(0 * 3 + 2) * 64 + 2 * k + 1] = 0.f;
                float i1r = cr,  i1i = ci;
                float i0r = i1r * cr - i1i * (-ci);
                float i0i = i1r * (-ci) + i1i * cr;
                g_fr[(1 * 3 + 0) * 64 + 2 * k] = i0r; g_fr[(1 * 3 + 0) * 64 + 2 * k + 1] = i0i;
                g_fr[(1 * 3 + 1) * 64 + 2 * k] = i1r; g_fr[(1 * 3 + 1) * 64 + 2 * k + 1] = i1i;
                g_fr[(1 * 3 + 2) * 64 + 2 * k] = 1.f; g_fr[(1 * 3 + 2) * 64 + 2 * k + 1] = 0.f;
            }
        }
    }

    const int NB0 = (N0v + 127) / 128;
    int bt = blockIdx.x;
    int tower = (bt >= NB0) ? 1 : 0;
    int bl = tower ? bt - NB0 : bt;
    int nbase = bl * 128;
    int Nlim = tower ? N1v : N0v;
    int valid = Nlim - nbase; if (valid > 128) valid = 128;
    const float* X  = tower ? feats1 : feats0;
    const float* PW = tower ? pw1 : pw0;
    const float* PB = tower ? pb1 : pb0;
    const float* W2 = tower ? w21 : w20;
    const float* B2 = tower ? b21 : b20;
    const float* GG = tower ? gg1 : gg0;
    const float* BE = tower ? be1 : be0;
    const int*  IDX = tower ? idx1 : idx0;

    int ra    = lane & 15;
    int kadd  = (lane >> 4) * 8;
    int nB    = ((lane >> 4) << 3) + (lane & 7);
    int kB    = ((lane >> 3) & 1) * 8;

    float acc[8][4];
    #pragma unroll
    for (int nt = 0; nt < 8; nt++)
        #pragma unroll
        for (int i = 0; i < 4; i++) acc[nt][i] = 0.f;

    // =================== GEMM1: X[128x512] @ W1[512x64] ======================
    for (int c = 0; c < 8; c++) {
        #pragma unroll
        for (int it = 0; it < 8; it++) {
            int idx = tid + it * 256;
            int row = idx >> 4, q = idx & 15;
            int gr = nbase + row; if (gr >= Nlim) gr = Nlim - 1;
            float4 v = *(const float4*)&X[(size_t)gr * F0v + c * 64 + q * 4];
            uint2 H, L;
            split2(v.x, v.y, H.x, L.x);
            split2(v.z, v.w, H.y, L.y);
            uint32_t off = (uint32_t)(row * LDA + q * 4) * 2;
            *(uint2*)(sm + OF_AHI + off) = H;
            *(uint2*)(sm + OF_ALO + off) = L;
        }
        #pragma unroll
        for (int it = 0; it < 4; it++) {
            int idx = tid + it * 256;
            int k = idx >> 4, q = (idx & 15) * 4;
            float4 w = *(const float4*)&PW[(size_t)(c * 64 + k) * HIDv + q];
            float wv[4] = {w.x, w.y, w.z, w.w};
            #pragma unroll
            for (int j = 0; j < 4; j++) {
                int n = q + j;
                int kp = k ^ (((n >> 3) & 7) << 3);
                __nv_bfloat16 h = __float2bfloat16(wv[j]);
                __nv_bfloat16 l = __float2bfloat16(wv[j] - __bfloat162float(h));
                uint32_t off = (uint32_t)(n * LDA + kp) * 2;
                *(__nv_bfloat16*)(sm + OF_BHI + off) = h;
                *(__nv_bfloat16*)(sm + OF_BLO + off) = l;
            }
        }
        __syncthreads();
        #pragma unroll
        for (int ks = 0; ks < 4; ks++) {
            uint32_t ahi[4], alo[4], bh[16], blo[16];
            uint32_t aoff = (uint32_t)((wid * 16 + ra) * LDA + ks * 16 + kadd) * 2;
            ldsm4(sbase + OF_AHI + aoff, ahi);
            ldsm4(sbase + OF_ALO + aoff, alo);
            #pragma unroll
            for (int ng = 0; ng < 4; ng++) {
                int n = ng * 16 + nB;
                int kp = (ks * 16 + kB) ^ (((n >> 3) & 7) << 3);
                uint32_t boff = (uint32_t)(n * LDA + kp) * 2;
                ldsm4(sbase + OF_BHI + boff, &bh[ng * 4]);
                ldsm4(sbase + OF_BLO + boff, &blo[ng * 4]);
            }
            #pragma unroll
            for (int nt = 0; nt < 8; nt++) {
                mma16816(acc[nt], ahi, &bh[nt * 2]);
                mma16816(acc[nt], ahi, &blo[nt * 2]);
                mma16816(acc[nt], alo, &bh[nt * 2]);
            }
        }
        __syncthreads();
    }

    // =================== z = acc + b1; h = gelu(z) -> A smem =================
    int nlo = 2 * (lane & 3);
    int r0 = wid * 16 + (lane >> 2);
    int r1 = r0 + 8;
    float z[8][4];
    #pragma unroll
    for (int nt = 0; nt < 8; nt++) {
        float b0 = PB[nt * 8 + nlo], b1v = PB[nt * 8 + nlo + 1];
        z[nt][0] = acc[nt][0] + b0;  z[nt][1] = acc[nt][1] + b1v;
        z[nt][2] = acc[nt][2] + b0;  z[nt][3] = acc[nt][3] + b1v;
        float h0 = 0.5f * z[nt][0] * (1.f + erff(z[nt][0] * 0.70710678118654752f));
        float h1 = 0.5f * z[nt][1] * (1.f + erff(z[nt][1] * 0.70710678118654752f));
        float h2 = 0.5f * z[nt][2] * (1.f + erff(z[nt][2] * 0.70710678118654752f));
        float h3 = 0.5f * z[nt][3] * (1.f + erff(z[nt][3] * 0.70710678118654752f));
        uint32_t H01, L01, H23, L23;
        split2(h0, h1, H01, L01);
        split2(h2, h3, H23, L23);
        uint32_t o0 = (uint32_t)(r0 * LDA + nt * 8 + nlo) * 2;
        uint32_t o1 = (uint32_t)(r1 * LDA + nt * 8 + nlo) * 2;
        *(uint32_t*)(sm + OF_AHI + o0) = H01;
        *(uint32_t*)(sm + OF_ALO + o0) = L01;
        *(uint32_t*)(sm + OF_AHI + o1) = H23;
        *(uint32_t*)(sm + OF_ALO + o1) = L23;
        acc[nt][0] = 0.f; acc[nt][1] = 0.f; acc[nt][2] = 0.f; acc[nt][3] = 0.f;
    }
    #pragma unroll
    for (int it = 0; it < 4; it++) {
        int idx = tid + it * 256;
        int k = idx >> 4, q = (idx & 15) * 4;
        float4 w = *(const float4*)&W2[(size_t)k * HIDv + q];
        float wv[4] = {w.x, w.y, w.z, w.w};
        #pragma unroll
        for (int j = 0; j < 4; j++) {
            int n = q + j;
            int kp = k ^ (((n >> 3) & 7) << 3);
            __nv_bfloat16 h = __float2bfloat16(wv[j]);
            __nv_bfloat16 l = __float2bfloat16(wv[j] - __bfloat162float(h));
            uint32_t off = (uint32_t)(n * LDA + kp) * 2;
            *(__nv_bfloat16*)(sm + OF_BHI + off) = h;
            *(__nv_bfloat16*)(sm + OF_BLO + off) = l;
        }
    }
    __syncthreads();

    // =================== GEMM2: h[128x64] @ W2[64x64] ========================
    #pragma unroll
    for (int ks = 0; ks < 4; ks++) {
        uint32_t ahi[4], alo[4], bh[16], blo[16];
        uint32_t aoff = (uint32_t)((wid * 16 + ra) * LDA + ks * 16 + kadd) * 2;
        ldsm4(sbase + OF_AHI + aoff, ahi);
        ldsm4(sbase + OF_ALO + aoff, alo);
        #pragma unroll
        for (int ng = 0; ng < 4; ng++) {
            int n = ng * 16 + nB;
            int kp = (ks * 16 + kB) ^ (((n >> 3) & 7) << 3);
            uint32_t boff = (uint32_t)(n * LDA + kp) * 2;
            ldsm4(sbase + OF_BHI + boff, &bh[ng * 4]);
            ldsm4(sbase + OF_BLO + boff, &blo[ng * 4]);
        }
        #pragma unroll
        for (int nt = 0; nt < 8; nt++) {
            mma16816(acc[nt], ahi, &bh[nt * 2]);
            mma16816(acc[nt], ahi, &blo[nt * 2]);
            mma16816(acc[nt], alo, &bh[nt * 2]);
        }
    }

    // =================== y = acc + b2 + z; LayerNorm; store ==================
    float y[8][4];
    float s1a = 0.f, s2a = 0.f, s1b = 0.f, s2b = 0.f;
    #pragma unroll
    for (int nt = 0; nt < 8; nt++) {
        float b0 = B2[nt * 8 + nlo], b1v = B2[nt * 8 + nlo + 1];
        y[nt][0] = acc[nt][0] + b0 + z[nt][0];
        y[nt][1] = acc[nt][1] + b1v + z[nt][1];
        y[nt][2] = acc[nt][2] + b0 + z[nt][2];
        y[nt][3] = acc[nt][3] + b1v + z[nt][3];
        s1a += y[nt][0] + y[nt][1];
        s2a += y[nt][0] * y[nt][0] + y[nt][1] * y[nt][1];
        s1b += y[nt][2] + y[nt][3];
        s2b += y[nt][2] * y[nt][2] + y[nt][3] * y[nt][3];
    }
    #pragma unroll
    for (int m = 1; m < 4; m <<= 1) {
        s1a += __shfl_xor_sync(0xffffffffu, s1a, m);
        s2a += __shfl_xor_sync(0xffffffffu, s2a, m);
        s1b += __shfl_xor_sync(0xffffffffu, s1b, m);
        s2b += __shfl_xor_sync(0xffffffffu, s2b, m);
    }
    float mu0 = s1a * (1.f / 64.f);
    float rs0 = rsqrtf(s2a * (1.f / 64.f) - mu0 * mu0 + 1e-5f);
    float mu1 = s1b * (1.f / 64.f);
    float rs1 = rsqrtf(s2b * (1.f / 64.f) - mu1 * mu1 + 1e-5f);
    if (r0 < valid) {
        int gn = IDX[nbase + r0];
        #pragma unroll
        for (int nt = 0; nt < 8; nt++) {
            float2 o;
            o.x = (y[nt][0] - mu0) * rs0 * GG[nt * 8 + nlo] + BE[nt * 8 + nlo];
            o.y = (y[nt][1] - mu0) * rs0 * GG[nt * 8 + nlo + 1] + BE[nt * 8 + nlo + 1];
            *(float2*)&g_feat[(size_t)gn * HIDv + nt * 8 + nlo] = o;
        }
    }
    if (r1 < valid) {
        int gn = IDX[nbase + r1];
        #pragma unroll
        for (int nt = 0; nt < 8; nt++) {
            float2 o;
            o.x = (y[nt][2] - mu1) * rs1 * GG[nt * 8 + nlo] + BE[nt * 8 + nlo];
            o.y = (y[nt][3] - mu1) * rs1 * GG[nt * 8 + nlo + 1] + BE[nt * 8 + nlo + 1];
            *(float2*)&g_feat[(size_t)gn * HIDv + nt * 8 + nlo] = o;
        }
    }
}

// ---- fused metapath: gather+rotate+mean -> e -> exp -> seg sums (no max) ----
__global__ __launch_bounds__(256) void k_mpf(
    const int* __restrict__ emi_u, const int* __restrict__ tgt_u,
    const int* __restrict__ emi_i, const int* __restrict__ tgt_i,
    const float* __restrict__ attn_u, const float* __restrict__ attn_i)
{
    int warp = blockIdx.x * (blockDim.x >> 5) + (threadIdx.x >> 5);
    int lane = threadIdx.x & 31;
    int half = lane >> 4;
    int sl = lane & 15;
    int inst = warp * 2 + half;
    int p = inst / EPM;
    int i = inst - p * EPM;
    int side = p >> 1, pl = p & 1;
    const int* emi = side ? emi_i : emi_u;
    const int* tgt = side ? tgt_i : tgt_u;
    const float* attn = side ? attn_i : attn_u;

    int n = 0;
    if (sl < 3) n = emi[((size_t)pl * EPM + i) * 3 + sl];
    float re0 = 0.f, im0 = 0.f, re1 = 0.f, im1 = 0.f;
    #pragma unroll
    for (int l = 0; l < 3; l++) {
        int nl = __shfl_sync(0xffffffffu, n, half * 16 + l);
        float4 v  = *(const float4*)&g_feat[(size_t)nl * HIDv + sl * 4];
        float4 fr = *(const float4*)&g_fr[(side * 3 + l) * 64 + sl * 4];
        re0 += v.x * fr.x - v.y * fr.y;
        im0 += v.x * fr.y + v.y * fr.x;
        re1 += v.z * fr.z - v.w * fr.w;
        im1 += v.z * fr.w + v.w * fr.z;
    }
    re0 *= (1.f / 3.f); im0 *= (1.f / 3.f);
    re1 *= (1.f / 3.f); im1 *= (1.f / 3.f);

    int h = sl >> 1;
    int dpart = (sl & 1) * 4;
    float4 av = *(const float4*)&attn[(pl * 8 + h) * 8 + dpart];
    float ep = re0 * av.x + im0 * av.y + re1 * av.z + im1 * av.w;
    ep += __shfl_xor_sync(0xffffffffu, ep, 1);
    float ev = ep > 0.f ? ep : 0.01f * ep;
    float a = __expf(ev);

    int t = tgt[(size_t)pl * EPM + i];
    size_t seg = (size_t)p * BTv + t;
    if ((sl & 1) == 0) atomicAdd(&g_s[seg * 8 + h], a);
    atomicAdd((float4*)&g_ret[seg * HIDv + sl * 4],
              make_float4(a * re0, a * im0, a * re1, a * im1));
}

// -------- semantic via mma.sync: 128 rows x 128 cols per block ---------------
#define S_LDA 72
#define S_AHI 0
#define S_ALO 18432
#define S_BHI 36864
#define S_BLO 55296
#define S_TOT 73728

__global__ __launch_bounds__(256) void k_sem_mma(
    const float* __restrict__ su_w1, const float* __restrict__ su_b1, const float* __restrict__ su_w2,
    const float* __restrict__ si_w1, const float* __restrict__ si_b1, const float* __restrict__ si_w2)
{
    extern __shared__ __align__(16) char sm2[];
    uint32_t sbase = smem_u32(sm2);
    __shared__ float red[8];
    int p = blockIdx.y;
    const float* w1 = (p < 2) ? su_w1 : si_w1;
    const float* b1 = (p < 2) ? su_b1 : si_b1;
    const float* w2 = (p < 2) ? su_w2 : si_w2;
    int tid = threadIdx.x;
    int lane = tid & 31;
    int wid = tid >> 5;

    #pragma unroll
    for (int it = 0; it < 8; it++) {
        int idx = tid + it * 256;
        int k = idx >> 5;
        int q = (idx & 31) * 4;
        float4 w = *(const float4*)&w1[(size_t)k * 128 + q];
        float wv[4] = {w.x, w.y, w.z, w.w};
        #pragma unroll
        for (int j = 0; j < 4; j++) {
            int n = q + j;
            int kp = k ^ (((n >> 3) & 7) << 3);
            __nv_bfloat16 h = __float2bfloat16(wv[j]);
            __nv_bfloat16 l = __float2bfloat16(wv[j] - __bfloat162float(h));
            uint32_t off = (uint32_t)(n * S_LDA + kp) * 2;
            *(__nv_bfloat16*)(sm2 + S_BHI + off) = h;
            *(__nv_bfloat16*)(sm2 + S_BLO + off) = l;
        }
    }
    {
        int row = tid >> 1;
        int b_g = blockIdx.x * 128 + row;
        size_t seg = (size_t)p * BTv + b_g;
        int cbase = (tid & 1) * 32;
        #pragma unroll
        for (int cc = 0; cc < 8; cc++) {
            int c0 = cbase + cc * 4;
            float sd = g_s[seg * 8 + (c0 >> 3)] + 1e-9f;
            float inv = 1.f / sd;
            float4 v = *(const float4*)&g_ret[seg * HIDv + c0];
            v.x *= inv; v.y *= inv; v.z *= inv; v.w *= inv;
            v.x = v.x > 0.f ? v.x : expf(v.x) - 1.f;
            v.y = v.y > 0.f ? v.y : expf(v.y) - 1.f;
            v.z = v.z > 0.f ? v.z : expf(v.z) - 1.f;
            v.w = v.w > 0.f ? v.w : expf(v.w) - 1.f;
            *(float4*)&g_ret[seg * HIDv + c0] = v;    // persist for k_final
            uint2 H, L;
            split2(v.x, v.y, H.x, L.x);
            split2(v.z, v.w, H.y, L.y);
            uint32_t off = (uint32_t)(row * S_LDA + c0) * 2;
            *(uint2*)(sm2 + S_AHI + off) = H;
            *(uint2*)(sm2 + S_ALO + off) = L;
        }
    }
    __syncthreads();

    int ra   = lane & 15;
    int kadd = (lane >> 4) * 8;
    int nB   = ((lane >> 4) << 3) + (lane & 7);
    int kB   = ((lane >> 3) & 1) * 8;

    float acc[16][4];
    #pragma unroll
    for (int t = 0; t < 16; t++)
        #pragma unroll
        for (int i = 0; i < 4; i++) acc[t][i] = 0.f;

    #pragma unroll
    for (int ks = 0; ks < 4; ks++) {
        uint32_t ahi[4], alo[4];
        uint32_t aoff = (uint32_t)((wid * 16 + ra) * S_LDA + ks * 16 + kadd) * 2;
        ldsm4(sbase + S_AHI + aoff, ahi);
        ldsm4(sbase + S_ALO + aoff, alo);
        #pragma unroll
        for (int ng = 0; ng < 8; ng++) {
            int n = ng * 16 + nB;
            int kp = (ks * 16 + kB) ^ (((n >> 3) & 7) << 3);
            uint32_t boff = (uint32_t)(n * S_LDA + kp) * 2;
            uint32_t bh[4], blo[4];
            ldsm4(sbase + S_BHI + boff, bh);
            ldsm4(sbase + S_BLO + boff, blo);
            mma16816(acc[ng * 2 + 0], ahi, &bh[0]);
            mma16816(acc[ng * 2 + 0], ahi, &blo[0]);
            mma16816(acc[ng * 2 + 0], alo, &bh[0]);
            mma16816(acc[ng * 2 + 1], ahi, &bh[2]);
            mma16816(acc[ng * 2 + 1], ahi, &blo[2]);
            mma16816(acc[ng * 2 + 1], alo, &bh[2]);
        }
    }

    float lsum = 0.f;
    #pragma unroll
    for (int t = 0; t < 16; t++) {
        int col = (t >> 1) * 16 + (t & 1) * 8 + 2 * (lane & 3);
        float bb0 = b1[col], bb1 = b1[col + 1];
        float ww0 = w2[col], ww1 = w2[col + 1];
        lsum += tanhf(acc[t][0] + bb0) * ww0 + tanhf(acc[t][1] + bb1) * ww1
              + tanhf(acc[t][2] + bb0) * ww0 + tanhf(acc[t][3] + bb1) * ww1;
    }
    #pragma unroll
    for (int m = 16; m; m >>= 1) lsum += __shfl_xor_sync(0xffffffffu, lsum, m);
    if (lane == 0) red[wid] = lsum;
    __syncthreads();
    if (tid == 0) {
        float s = 0.f;
        #pragma unroll
        for (int w = 0; w < 8; w++) s += red[w];
        atomicAdd(&g_score[p], s);
    }
}

// -------- final via mma.sync: 64 rows x 128 cols per block (grid 128) --------
__global__ __launch_bounds__(128) void k_final_mma(
    const float* __restrict__ cw1, const float* __restrict__ cb1,
    const float* __restrict__ cw2, float* __restrict__ out)
{
    extern __shared__ __align__(16) char sm3[];
    uint32_t sbase = smem_u32(sm3);
    int tid = threadIdx.x;
    int lane = tid & 31;
    int wid = tid >> 5;           // 0..3

    float s0 = g_score[0] * (1.f / BTv), s1 = g_score[1] * (1.f / BTv);
    float s2 = g_score[2] * (1.f / BTv), s3 = g_score[3] * (1.f / BTv);
    float mu = fmaxf(s0, s1);
    float e0 = __expf(s0 - mu), e1 = __expf(s1 - mu);
    float bu0 = e0 / (e0 + e1), bu1 = e1 / (e0 + e1);
    float mi = fmaxf(s2, s3);
    float e2 = __expf(s2 - mi), e3 = __expf(s3 - mi);
    float bi0 = e2 / (e2 + e3), bi1 = e3 / (e2 + e3);

    // cw1[64k x 128n] -> B smem [n][k^swz] bf16 hi/lo (A region holds 64 rows)
    #pragma unroll
    for (int it = 0; it < 16; it++) {
        int idx = tid + it * 128;
        int k = idx >> 5;
        int q = (idx & 31) * 4;
        float4 w = *(const float4*)&cw1[(size_t)k * 128 + q];
        float wv[4] = {w.x, w.y, w.z, w.w};
        #pragma unroll
        for (int j = 0; j < 4; j++) {
            int n = q + j;
            int kp = k ^ (((n >> 3) & 7) << 3);
            __nv_bfloat16 h = __float2bfloat16(wv[j]);
            __nv_bfloat16 l = __float2bfloat16(wv[j] - __bfloat162float(h));
            uint32_t off = (uint32_t)(n * S_LDA + kp) * 2;
            *(__nv_bfloat16*)(sm3 + S_BHI + off) = h;
            *(__nv_bfloat16*)(sm3 + S_BLO + off) = l;
        }
    }
    // rows: beta-combine + product -> A smem bf16 hi/lo (64 rows, 2 thr/row)
    {
        int row = tid >> 1;
        int b_g = blockIdx.x * 64 + row;
        size_t o = (size_t)b_g * HIDv;
        int cbase = (tid & 1) * 32;
        #pragma unroll
        for (int cc = 0; cc < 8; cc++) {
            int c0 = cbase + cc * 4;
            float4 r0 = *(const float4*)&g_ret[o + c0];
            float4 r1 = *(const float4*)&g_ret[(size_t)BTv * HIDv + o + c0];
            float4 r2 = *(const float4*)&g_ret[(size_t)2 * BTv * HIDv + o + c0];
            float4 r3 = *(const float4*)&g_ret[(size_t)3 * BTv * HIDv + o + c0];
            float4 v;
            v.x = (bu0 * r0.x + bu1 * r1.x) * (bi0 * r2.x + bi1 * r3.x);
            v.y = (bu0 * r0.y + bu1 * r1.y) * (bi0 * r2.y + bi1 * r3.y);
            v.z = (bu0 * r0.z + bu1 * r1.z) * (bi0 * r2.z + bi1 * r3.z);
            v.w = (bu0 * r0.w + bu1 * r1.w) * (bi0 * r2.w + bi1 * r3.w);
            uint2 H, L;
            split2(v.x, v.y, H.x, L.x);
            split2(v.z, v.w, H.y, L.y);
            uint32_t off = (uint32_t)(row * S_LDA + c0) * 2;
            *(uint2*)(sm3 + S_AHI + off) = H;
            *(uint2*)(sm3 + S_ALO + off) = L;
        }
    }
    __syncthreads();

    int ra   = lane & 15;
    int kadd = (lane >> 4) * 8;
    int nB   = ((lane >> 4) << 3) + (lane & 7);
    int kB   = ((lane >> 3) & 1) * 8;

    float acc[16][4];
    #pragma unroll
    for (int t = 0; t < 16; t++)
        #pragma unroll
        for (int i = 0; i < 4; i++) acc[t][i] = 0.f;

    #pragma unroll
    for (int ks = 0; ks < 4; ks++) {
        uint32_t ahi[4], alo[4];
        uint32_t aoff = (uint32_t)((wid * 16 + ra) * S_LDA + ks * 16 + kadd) * 2;
        ldsm4(sbase + S_AHI + aoff, ahi);
        ldsm4(sbase + S_ALO + aoff, alo);
        #pragma unroll
        for (int ng = 0; ng < 8; ng++) {
            int n = ng * 16 + nB;
            int kp = (ks * 16 + kB) ^ (((n >> 3) & 7) << 3);
            uint32_t boff = (uint32_t)(n * S_LDA + kp) * 2;
            uint32_t bh[4], blo[4];
            ldsm4(sbase + S_BHI + boff, bh);
            ldsm4(sbase + S_BLO + boff, blo);
            mma16816(acc[ng * 2 + 0], ahi, &bh[0]);
            mma16816(acc[ng * 2 + 0], ahi, &blo[0]);
            mma16816(acc[ng * 2 + 0], alo, &bh[0]);
            mma16816(acc[ng * 2 + 1], ahi, &bh[2]);
            mma16816(acc[ng * 2 + 1], ahi, &blo[2]);
            mma16816(acc[ng * 2 + 1], alo, &bh[2]);
        }
    }

    // epilogue: relu, dot with cw2, reduce cols across 4-lane group, softmax
    float l0a = 0.f, l1a = 0.f, l0b = 0.f, l1b = 0.f;
    #pragma unroll
    for (int t = 0; t < 16; t++) {
        int col = (t >> 1) * 16 + (t & 1) * 8 + 2 * (lane & 3);
        float bb0 = cb1[col], bb1 = cb1[col + 1];
        float wa0 = cw2[col * 2 + 0],       wb0 = cw2[col * 2 + 1];
        float wa1 = cw2[(col + 1) * 2 + 0], wb1 = cw2[(col + 1) * 2 + 1];
        float h;
        h = fmaxf(acc[t][0] + bb0, 0.f); l0a += h * wa0; l1a += h * wb0;
        h = fmaxf(acc[t][1] + bb1, 0.f); l0a += h * wa1; l1a += h * wb1;
        h = fmaxf(acc[t][2] + bb0, 0.f); l0b += h * wa0; l1b += h * wb0;
        h = fmaxf(acc[t][3] + bb1, 0.f); l0b += h * wa1; l1b += h * wb1;
    }
    #pragma unroll
    for (int m = 1; m < 4; m <<= 1) {
        l0a += __shfl_xor_sync(0xffffffffu, l0a, m);
        l1a += __shfl_xor_sync(0xffffffffu, l1a, m);
        l0b += __shfl_xor_sync(0xffffffffu, l0b, m);
        l1b += __shfl_xor_sync(0xffffffffu, l1b, m);
    }
    if ((lane & 3) == 0) {
        int r0 = blockIdx.x * 64 + wid * 16 + (lane >> 2);
        float mm = fmaxf(l0a, l1a);
        float ea = __expf(l0a - mm), eb = __expf(l1a - mm);
        float inv = 1.f / (ea + eb);
        out[r0 * 2 + 0] = ea * inv;
        out[r0 * 2 + 1] = eb * inv;
        int r1 = r0 + 8;
        mm = fmaxf(l0b, l1b);
        ea = __expf(l0b - mm); eb = __expf(l1b - mm);
        inv = 1.f / (ea + eb);
        out[r1 * 2 + 0] = ea * inv;
        out[r1 * 2 + 1] = eb * inv;
    }
}

// -----------------------------------------------------------------------------
extern "C" void kernel_launch(void* const* d_in, const int* in_sizes, int n_in,
                              void* d_out, int out_size)
{
    const float* feats0 = (const float*)d_in[0];
    const float* feats1 = (const float*)d_in[1];
    const float* t0_pw  = (const float*)d_in[2];
    const float* t0_pb  = (const float*)d_in[3];
    const float* t0_w2  = (const float*)d_in[4];
    const float* t0_b2  = (const float*)d_in[5];
    const float* t0_g   = (const float*)d_in[6];
    const float* t0_be  = (const float*)d_in[7];
    const float* t1_pw  = (const float*)d_in[8];
    const float* t1_pb  = (const float*)d_in[9];
    const float* t1_w2  = (const float*)d_in[10];
    const float* t1_b2  = (const float*)d_in[11];
    const float* t1_g   = (const float*)d_in[12];
    const float* t1_be  = (const float*)d_in[13];
    const float* r_vec  = (const float*)d_in[14];
    const float* attn_u = (const float*)d_in[15];
    const float* attn_i = (const float*)d_in[16];
    const float* su_w1  = (const float*)d_in[17];
    const float* su_b1  = (const float*)d_in[18];
    const float* su_w2  = (const float*)d_in[19];
    const float* si_w1  = (const float*)d_in[20];
    const float* si_b1  = (const float*)d_in[21];
    const float* si_w2  = (const float*)d_in[22];
    const float* cw1    = (const float*)d_in[23];
    const float* cb1    = (const float*)d_in[24];
    const float* cw2    = (const float*)d_in[25];
    const int*   idx0   = (const int*)d_in[26];
    const int*   idx1   = (const int*)d_in[27];
    const int*   emi_u  = (const int*)d_in[28];
    const int*   tgt_u  = (const int*)d_in[29];
    const int*   emi_i  = (const int*)d_in[30];
    const int*   tgt_i  = (const int*)d_in[31];

    static int smem_set = 0;
    if (!smem_set) {
        cudaFuncSetAttribute(k_tower_mma, cudaFuncAttributeMaxDynamicSharedMemorySize, SMTOT);
        cudaFuncSetAttribute(k_sem_mma, cudaFuncAttributeMaxDynamicSharedMemorySize, S_TOT);
        cudaFuncSetAttribute(k_final_mma, cudaFuncAttributeMaxDynamicSharedMemorySize, S_TOT);
        smem_set = 1;
    }

    int NBT = (N0v + 127) / 128 + (N1v + 127) / 128;
    k_tower_mma<<<NBT, 256, SMTOT>>>(feats0, feats1,
        t0_pw, t0_pb, t0_w2, t0_b2, t0_g, t0_be,
        t1_pw, t1_pb, t1_w2, t1_b2, t1_g, t1_be, idx0, idx1, r_vec);
    k_mpf<<<NPv * EPM / 16, 256>>>(emi_u, tgt_u, emi_i, tgt_i, attn_u, attn_i);
    dim3 gsem(BTv / 128, NPv);
    k_sem_mma<<<gsem, 256, S_TOT>>>(su_w1, su_b1, su_w2, si_w1, si_b1, si_w2);
    k_final_mma<<<BTv / 64, 128, S_TOT>>>(cw1, cb1, cw2, (float*)d_out);
}